// round 2
// baseline (speedup 1.0000x reference)
#include <cuda_runtime.h>

#define NN 48
#define BATCH 4
#define CC 32
#define NSITES (BATCH*NN*NN*NN)
#define TSIZE  ((size_t)NSITES*CC)

__device__ float g_t[TSIZE];
__device__ float g_v[TSIZE];
__device__ float g_w[TSIZE];
__device__ float g_D [BATCH*NN*NN*CC];
__device__ float g_Cc[BATCH*NN*NN*CC];
__device__ float g_G [BATCH*NN*CC];
__device__ int   g_mask_mode;
__device__ float g_nv[BATCH*NN];

// constant weight staging (floats)
// [0 .. 6*CC*COUT)  basic W (6 ops);  [6*CC*COUT .. +COUT) basic bias
// layers (COUT=32): Wv@6176, Ww@7200, Wo@8224, bv@9248, bw@9280, bo@9312
#define OFF_WV 6176
#define OFF_WW 7200
#define OFF_WO 8224
#define OFF_BV 9248
#define OFF_BW 9280
#define OFF_BO 9312
__constant__ float cb[9344];

// ---------- mask dtype detection + node_valid extraction ----------
__global__ void k_detect(const unsigned char* __restrict__ mask) {
    if (threadIdx.x == 0) {
        unsigned char b0 = mask[0], b1 = mask[1];
        int mode;
        if (b0 == 1 && b1 != 0) mode = 0;      // 1-byte bool
        else if (b0 == 1)       mode = 1;      // int32
        else                    mode = 2;      // float32
        g_mask_mode = mode;
    }
}
__global__ void k_nodevalid(const void* __restrict__ mask) {
    int p = threadIdx.x;
    if (p < BATCH*NN) {
        int b = p / NN, i = p % NN;
        size_t idx = (((size_t)b*NN + i)*NN + i)*NN + i;
        int mode = g_mask_mode;
        float v;
        if (mode == 0)      v = ((const unsigned char*)mask)[idx] ? 1.f : 0.f;
        else if (mode == 1) v = ((const int*)mask)[idx] ? 1.f : 0.f;
        else                v = (((const float*)mask)[idx] != 0.f) ? 1.f : 0.f;
        g_nv[p] = v;
    }
}

// ---------- t[b,i,j,m,c] = x[b,i,c]*x[b,j,c]*x[b,m,c] * mask ----------
__global__ __launch_bounds__(256) void k_build_t(const float* __restrict__ x) {
    int s = blockIdx.x * 256 + threadIdx.x;
    int m = s % NN, j = (s / NN) % NN, i = (s / (NN*NN)) % NN, b = s / (NN*NN*NN);
    float mv = g_nv[b*NN+i] * g_nv[b*NN+j] * g_nv[b*NN+m];
    const float4* xi = (const float4*)(x + (b*NN + i)*CC);
    const float4* xj = (const float4*)(x + (b*NN + j)*CC);
    const float4* xm = (const float4*)(x + (b*NN + m)*CC);
    float4* out = (float4*)(g_t + (size_t)s * CC);
#pragma unroll
    for (int q = 0; q < 8; q++) {
        float4 a = xi[q], c = xj[q], d = xm[q], r;
        r.x = a.x*c.x*d.x*mv; r.y = a.y*c.y*d.y*mv;
        r.z = a.z*c.z*d.z*mv; r.w = a.w*c.w*d.w*mv;
        out[q] = r;
    }
}

// ---------- per (b,m): rows/cols/diag/tot, contract W2..W5 + bias ----------
template<int COUT>
__global__ __launch_bounds__(256) void k_reduce() {
    __shared__ float rows[NN*CC], cols[NN*CC], diag[NN*CC], tots[CC];
    int bm = blockIdx.x;
    int m = bm % NN, b = bm / NN;

    for (int p = threadIdx.x; p < NN*CC; p += 256) {
        int i = p / CC, c = p % CC;
        const float* pt = g_t + ((((size_t)b*NN + i)*NN + 0)*NN + m)*CC + c;
        float acc = 0.f;
#pragma unroll 8
        for (int j = 0; j < NN; j++) acc += pt[(size_t)j * (NN*CC)];
        rows[p] = acc * (1.0f/NN);
        diag[p] = pt[(size_t)i * (NN*CC)];
    }
    for (int p = threadIdx.x; p < NN*CC; p += 256) {
        int j = p / CC, c = p % CC;
        const float* pt = g_t + ((((size_t)b*NN + 0)*NN + j)*NN + m)*CC + c;
        float acc = 0.f;
#pragma unroll 8
        for (int i = 0; i < NN; i++) acc += pt[(size_t)i * (NN*NN*CC)];
        cols[p] = acc * (1.0f/NN);
    }
    __syncthreads();
    if (threadIdx.x < CC) {
        float a = 0.f;
        for (int i = 0; i < NN; i++) a += rows[i*CC + threadIdx.x];
        tots[threadIdx.x] = a * (1.0f/NN);
    }
    __syncthreads();

    for (int p = threadIdx.x; p < NN*COUT; p += 256) {
        int i = p / COUT, d = p % COUT;
        float accD = 0.f, accC = 0.f;
#pragma unroll 8
        for (int c = 0; c < CC; c++) {
            accD += diag[i*CC + c] * cb[2*CC*COUT + c*COUT + d]
                  + rows[i*CC + c] * cb[3*CC*COUT + c*COUT + d];
            accC += cols[i*CC + c] * cb[4*CC*COUT + c*COUT + d];
        }
        g_D [((b*NN + i)*NN + m)*CC + d] = accD;
        g_Cc[((b*NN + i)*NN + m)*CC + d] = accC;
    }
    if (threadIdx.x < COUT) {
        int d = threadIdx.x;
        float a = cb[6*CC*COUT + d];           // basic bias
#pragma unroll 8
        for (int c = 0; c < CC; c++) a += tots[c] * cb[5*CC*COUT + c*COUT + d];
        g_G[(b*NN + m)*CC + d] = a;
    }
}

// ---------- fused snconv main (+mask) -> v/w projections or final out ----------
template<int COUT, bool FIN>
__global__ __launch_bounds__(128) void k_conv(float* __restrict__ out_final) {
    int s = blockIdx.x * 128 + threadIdx.x;
    int m = s % NN, j = (s / NN) % NN, i = (s / (NN*NN)) % NN, b = s / (NN*NN*NN);

    const float* tv = g_t + (size_t)s * CC;
    const float* tt = g_t + ((((size_t)b*NN + j)*NN + i)*NN + m) * CC;

    float acc[COUT];
#pragma unroll
    for (int d = 0; d < COUT; d++) acc[d] = 0.f;

#pragma unroll 1
    for (int c0 = 0; c0 < CC; c0 += 8) {
        float ta[8], tb8[8];
        float4 q;
        q = *(const float4*)(tv + c0);     ta[0]=q.x; ta[1]=q.y; ta[2]=q.z; ta[3]=q.w;
        q = *(const float4*)(tv + c0 + 4); ta[4]=q.x; ta[5]=q.y; ta[6]=q.z; ta[7]=q.w;
        q = *(const float4*)(tt + c0);     tb8[0]=q.x; tb8[1]=q.y; tb8[2]=q.z; tb8[3]=q.w;
        q = *(const float4*)(tt + c0 + 4); tb8[4]=q.x; tb8[5]=q.y; tb8[6]=q.z; tb8[7]=q.w;
#pragma unroll
        for (int cc = 0; cc < 8; cc++) {
            const float* w0 = cb + (c0 + cc)*COUT;
            const float* w1 = cb + CC*COUT + (c0 + cc)*COUT;
#pragma unroll
            for (int d = 0; d < COUT; d++)
                acc[d] += ta[cc]*w0[d] + tb8[cc]*w1[d];
        }
    }

    float mv = g_nv[b*NN+i] * g_nv[b*NN+j] * g_nv[b*NN+m];
    const float* Dp = g_D  + ((b*NN + i)*NN + m)*CC;
    const float* Cp = g_Cc + ((b*NN + j)*NN + m)*CC;
    const float* Gp = g_G  + (b*NN + m)*CC;
#pragma unroll
    for (int d = 0; d < COUT; d++)
        acc[d] = (acc[d] + Dp[d] + Cp[d] + Gp[d]) * mv;

    if (FIN) {
        float4* op = (float4*)(out_final + (size_t)s * COUT);
#pragma unroll
        for (int q4 = 0; q4 < COUT/4; q4++)
            op[q4] = make_float4(acc[q4*4+0], acc[q4*4+1], acc[q4*4+2], acc[q4*4+3]);
    } else {
        float pr[CC];
#pragma unroll
        for (int e = 0; e < CC; e++) pr[e] = cb[OFF_BV + e];
#pragma unroll 1
        for (int d = 0; d < COUT; d++) {
            float sd = acc[d];
            const float* wv = cb + OFF_WV + d*CC;
#pragma unroll
            for (int e = 0; e < CC; e++) pr[e] += sd * wv[e];
        }
        float4* vp = (float4*)(g_v + (size_t)s * CC);
#pragma unroll
        for (int q4 = 0; q4 < CC/4; q4++)
            vp[q4] = make_float4(pr[q4*4+0], pr[q4*4+1], pr[q4*4+2], pr[q4*4+3]);
#pragma unroll
        for (int e = 0; e < CC; e++) pr[e] = cb[OFF_BW + e];
#pragma unroll 1
        for (int d = 0; d < COUT; d++) {
            float sd = acc[d];
            const float* ww = cb + OFF_WW + d*CC;
#pragma unroll
            for (int e = 0; e < CC; e++) pr[e] += sd * ww[e];
        }
        float4* wp = (float4*)(g_w + (size_t)s * CC);
#pragma unroll
        for (int q4 = 0; q4 < CC/4; q4++)
            wp[q4] = make_float4(pr[q4*4+0], pr[q4*4+1], pr[q4*4+2], pr[q4*4+3]);
    }
}

// ---------- localconv: z = sum_k v⊙w / n, project Wo, relu, mask -> t ----------
#define WS_STRIDE 36
#define DSMEM_BYTES ((8*48*32 + 48*8*WS_STRIDE) * 4)

__global__ __launch_bounds__(128) void k_local() {
    extern __shared__ float sm[];
    float* vs = sm;                 // [8][48][32]
    float* ws = sm + 8*48*32;       // [48][8][WS_STRIDE]
    float* zs = sm;                 // alias after compute: [64][33]

    int blk = blockIdx.x;
    int jt6 = blk % 6, it6 = (blk / 6) % 6, m = (blk / 36) % NN, b = blk / (36*NN);
    int i0 = it6 * 8, j0 = jt6 * 8;
    int tid = threadIdx.x;

    for (int idx = tid; idx < 8*48*8; idx += 128) {
        int r = idx >> 3, c4 = idx & 7;
        int ii = r / 48, k = r % 48;
        float4 val = *(const float4*)(g_v + ((((size_t)b*NN + i0+ii)*NN + k)*NN + m)*CC + c4*4);
        *(float4*)(vs + r*32 + c4*4) = val;
    }
    for (int idx = tid; idx < 48*8*8; idx += 128) {
        int r = idx >> 3, c4 = idx & 7;
        int k = r / 8, jj = r % 8;
        float4 val = *(const float4*)(g_w + ((((size_t)b*NN + k)*NN + j0+jj)*NN + m)*CC + c4*4);
        *(float4*)(ws + r*WS_STRIDE + c4*4) = val;
    }
    __syncthreads();

    int ct = tid & 7, jt = (tid >> 3) & 3, it = tid >> 5;
    float a00[4]={0,0,0,0}, a01[4]={0,0,0,0}, a10[4]={0,0,0,0}, a11[4]={0,0,0,0};

#pragma unroll 4
    for (int k = 0; k < 48; k++) {
        float4 v0 = *(const float4*)(vs + ((it*2+0)*48 + k)*32 + ct*4);
        float4 v1 = *(const float4*)(vs + ((it*2+1)*48 + k)*32 + ct*4);
        float4 w0 = *(const float4*)(ws + (k*8 + jt*2+0)*WS_STRIDE + ct*4);
        float4 w1 = *(const float4*)(ws + (k*8 + jt*2+1)*WS_STRIDE + ct*4);
        a00[0]+=v0.x*w0.x; a00[1]+=v0.y*w0.y; a00[2]+=v0.z*w0.z; a00[3]+=v0.w*w0.w;
        a01[0]+=v0.x*w1.x; a01[1]+=v0.y*w1.y; a01[2]+=v0.z*w1.z; a01[3]+=v0.w*w1.w;
        a10[0]+=v1.x*w0.x; a10[1]+=v1.y*w0.y; a10[2]+=v1.z*w0.z; a10[3]+=v1.w*w0.w;
        a11[0]+=v1.x*w1.x; a11[1]+=v1.y*w1.y; a11[2]+=v1.z*w1.z; a11[3]+=v1.w*w1.w;
    }
    __syncthreads();

#pragma unroll
    for (int q = 0; q < 4; q++) {
        zs[((it*2+0)*8 + (jt*2+0))*33 + ct*4 + q] = a00[q];
        zs[((it*2+0)*8 + (jt*2+1))*33 + ct*4 + q] = a01[q];
        zs[((it*2+1)*8 + (jt*2+0))*33 + ct*4 + q] = a10[q];
        zs[((it*2+1)*8 + (jt*2+1))*33 + ct*4 + q] = a11[q];
    }
    __syncthreads();

    int site = tid >> 1, dh = tid & 1;
    float oa[16];
#pragma unroll
    for (int dd = 0; dd < 16; dd++) oa[dd] = 0.f;
#pragma unroll 4
    for (int c = 0; c < 32; c++) {
        float zv = zs[site*33 + c];
        const float* wo = cb + OFF_WO + c*32 + dh*16;
#pragma unroll
        for (int dd = 0; dd < 16; dd++) oa[dd] += zv * wo[dd];
    }
    int ii = site >> 3, jj = site & 7;
    int gi = i0 + ii, gj = j0 + jj;
    float mv = g_nv[b*NN+gi] * g_nv[b*NN+gj] * g_nv[b*NN+m];
    float res[16];
#pragma unroll
    for (int dd = 0; dd < 16; dd++) {
        float v = oa[dd] * (1.0f/NN) + cb[OFF_BO + dh*16 + dd];
        res[dd] = (v > 0.f ? v : 0.f) * mv;
    }
    float4* op = (float4*)(g_t + ((((size_t)b*NN + gi)*NN + gj)*NN + m)*CC + dh*16);
#pragma unroll
    for (int q4 = 0; q4 < 4; q4++)
        op[q4] = make_float4(res[q4*4+0], res[q4*4+1], res[q4*4+2], res[q4*4+3]);
}

// ---------- host ----------
static void stage_layer(void* const* d_in, int base) {
    cudaMemcpyToSymbolAsync(cb, d_in[base+0], 6144*4, 0,      cudaMemcpyDeviceToDevice, 0); // basic_W
    cudaMemcpyToSymbolAsync(cb, d_in[base+1],   32*4, 6144*4, cudaMemcpyDeviceToDevice, 0); // basic_b
    cudaMemcpyToSymbolAsync(cb, d_in[base+2], 1024*4, OFF_WV*4, cudaMemcpyDeviceToDevice, 0); // lv_W
    cudaMemcpyToSymbolAsync(cb, d_in[base+3],   32*4, OFF_BV*4, cudaMemcpyDeviceToDevice, 0); // lv_b
    cudaMemcpyToSymbolAsync(cb, d_in[base+4], 1024*4, OFF_WW*4, cudaMemcpyDeviceToDevice, 0); // lw_W
    cudaMemcpyToSymbolAsync(cb, d_in[base+5],   32*4, OFF_BW*4, cudaMemcpyDeviceToDevice, 0); // lw_b
    cudaMemcpyToSymbolAsync(cb, d_in[base+6], 1024*4, OFF_WO*4, cudaMemcpyDeviceToDevice, 0); // lo_W
    cudaMemcpyToSymbolAsync(cb, d_in[base+7],   32*4, OFF_BO*4, cudaMemcpyDeviceToDevice, 0); // lo_b
}

extern "C" void kernel_launch(void* const* d_in, const int* in_sizes, int n_in,
                              void* d_out, int out_size) {
    (void)in_sizes; (void)n_in; (void)out_size;
    const float* x = (const float*)d_in[0];
    const void*  mask = d_in[1];

    cudaFuncSetAttribute(k_local, cudaFuncAttributeMaxDynamicSharedMemorySize, DSMEM_BYTES);

    k_detect<<<1, 32>>>((const unsigned char*)mask);
    k_nodevalid<<<1, 256>>>(mask);
    k_build_t<<<NSITES/256, 256>>>(x);

    for (int l = 0; l < 2; l++) {
        stage_layer(d_in, 2 + 8*l);
        k_reduce<32><<<BATCH*NN, 256>>>();
        k_conv<32, false><<<NSITES/128, 128>>>(nullptr);
        k_local<<<BATCH*NN*36, 128, DSMEM_BYTES>>>();
    }

    cudaMemcpyToSymbolAsync(cb, d_in[18], 3072*4, 0,      cudaMemcpyDeviceToDevice, 0); // final_W
    cudaMemcpyToSymbolAsync(cb, d_in[19],   16*4, 3072*4, cudaMemcpyDeviceToDevice, 0); // final_b
    k_reduce<16><<<BATCH*NN, 256>>>();
    k_conv<16, true><<<NSITES/128, 128>>>((float*)d_out);
}

// round 3
// speedup vs baseline: 1.4022x; 1.4022x over previous
#include <cuda_runtime.h>

#define NN 48
#define BATCH 4
#define CC 32
#define NSITES (BATCH*NN*NN*NN)
#define TSIZE  ((size_t)NSITES*CC)
#define NIMC   (BATCH*NN*NN*CC)      // 294912

__device__ float g_t[TSIZE];
__device__ float g_v[TSIZE];
__device__ float g_w[TSIZE];
__device__ float g_rows[NIMC];
__device__ float g_cols[NIMC];
__device__ float g_diag[NIMC];
__device__ float g_D [NIMC];
__device__ float g_Cc[NIMC];
__device__ float g_G [BATCH*NN*CC];
__device__ int   g_mask_mode;
__device__ float g_nv[BATCH*NN];

// constant weight staging (floats)
// [0 .. 6*CC*COUT)  basic W (6 ops);  [6*CC*COUT .. +COUT) basic bias
// layers (COUT=32): Wv@6176, Ww@7200, Wo@8224, bv@9248, bw@9280, bo@9312
#define OFF_WV 6176
#define OFF_WW 7200
#define OFF_WO 8224
#define OFF_BV 9248
#define OFF_BW 9280
#define OFF_BO 9312
__constant__ float cb[9344];

// ---------- mask dtype detection + node_valid extraction ----------
__global__ void k_detect(const unsigned char* __restrict__ mask) {
    if (threadIdx.x == 0) {
        unsigned char b0 = mask[0], b1 = mask[1];
        int mode;
        if (b0 == 1 && b1 != 0) mode = 0;      // 1-byte bool
        else if (b0 == 1)       mode = 1;      // int32
        else                    mode = 2;      // float32
        g_mask_mode = mode;
    }
}
__global__ void k_nodevalid(const void* __restrict__ mask) {
    int p = threadIdx.x;
    if (p < BATCH*NN) {
        int b = p / NN, i = p % NN;
        size_t idx = (((size_t)b*NN + i)*NN + i)*NN + i;
        int mode = g_mask_mode;
        float v;
        if (mode == 0)      v = ((const unsigned char*)mask)[idx] ? 1.f : 0.f;
        else if (mode == 1) v = ((const int*)mask)[idx] ? 1.f : 0.f;
        else                v = (((const float*)mask)[idx] != 0.f) ? 1.f : 0.f;
        g_nv[p] = v;
    }
}

// ---------- t[b,i,j,m,c] = x[b,i,c]*x[b,j,c]*x[b,m,c] * mask ----------
__global__ __launch_bounds__(256) void k_build_t(const float* __restrict__ x) {
    int s = blockIdx.x * 256 + threadIdx.x;
    int m = s % NN, j = (s / NN) % NN, i = (s / (NN*NN)) % NN, b = s / (NN*NN*NN);
    float mv = g_nv[b*NN+i] * g_nv[b*NN+j] * g_nv[b*NN+m];
    const float4* xi = (const float4*)(x + (b*NN + i)*CC);
    const float4* xj = (const float4*)(x + (b*NN + j)*CC);
    const float4* xm = (const float4*)(x + (b*NN + m)*CC);
    float4* out = (float4*)(g_t + (size_t)s * CC);
#pragma unroll
    for (int q = 0; q < 8; q++) {
        float4 a = xi[q], c = xj[q], d = xm[q], r;
        r.x = a.x*c.x*d.x*mv; r.y = a.y*c.y*d.y*mv;
        r.z = a.z*c.z*d.z*mv; r.w = a.w*c.w*d.w*mv;
        out[q] = r;
    }
}

// ---------- stage 1: rows+diag / cols with one thread per output ----------
// blocks [0,1152): rows+diag over (b,i,m,c); blocks [1152,2304): cols over (b,j,m,c)
__global__ __launch_bounds__(256) void k_rowcol() {
    int blk = blockIdx.x;
    bool docols = blk >= (NIMC/256);
    int p = (docols ? blk - NIMC/256 : blk) * 256 + threadIdx.x;
    int c = p & 31;
    int m = (p >> 5) % NN;
    int a = (p / (32*NN)) % NN;          // i for rows, j for cols
    int b = p / (32*NN*NN);

    if (!docols) {
        const float* pt = g_t + ((((size_t)b*NN + a)*NN + 0)*NN + m)*CC + c;
        float s0=0.f, s1=0.f, s2=0.f, s3=0.f;
#pragma unroll
        for (int j = 0; j < NN; j += 4) {
            s0 += pt[(size_t)(j+0) * (NN*CC)];
            s1 += pt[(size_t)(j+1) * (NN*CC)];
            s2 += pt[(size_t)(j+2) * (NN*CC)];
            s3 += pt[(size_t)(j+3) * (NN*CC)];
        }
        g_rows[p] = (s0+s1+s2+s3) * (1.0f/NN);
        g_diag[p] = pt[(size_t)a * (NN*CC)];
    } else {
        const float* pt = g_t + ((((size_t)b*NN + 0)*NN + a)*NN + m)*CC + c;
        float s0=0.f, s1=0.f, s2=0.f, s3=0.f;
#pragma unroll
        for (int i = 0; i < NN; i += 4) {
            s0 += pt[(size_t)(i+0) * (NN*NN*CC)];
            s1 += pt[(size_t)(i+1) * (NN*NN*CC)];
            s2 += pt[(size_t)(i+2) * (NN*NN*CC)];
            s3 += pt[(size_t)(i+3) * (NN*NN*CC)];
        }
        g_cols[p] = (s0+s1+s2+s3) * (1.0f/NN);
    }
}

// ---------- stage 2: tot per (b,m) + G contraction ----------
template<int COUT>
__global__ __launch_bounds__(32) void k_totG(const float* __restrict__ W) {
    __shared__ float ts[CC];
    int bm = blockIdx.x;
    int m = bm % NN, b = bm / NN;
    int c = threadIdx.x;
    const float* pr = g_rows + (((size_t)b*NN + 0)*NN + m)*CC + c;
    float s = 0.f;
#pragma unroll
    for (int i = 0; i < NN; i++) s += pr[(size_t)i * (NN*CC)];
    ts[c] = s * (1.0f/NN);
    __syncwarp();
    if (c < COUT) {
        float a = cb[6*CC*COUT + c];       // basic bias (index by d=c)
#pragma unroll
        for (int c2 = 0; c2 < CC; c2++)
            a += ts[c2] * __ldg(W + (5*CC + c2)*COUT + c);
        g_G[(b*NN + m)*CC + c] = a;
    }
}

// ---------- stage 3: D = diag*W2 + rows*W3 ; Cc = cols*W4 ----------
template<int COUT>
__global__ __launch_bounds__(256) void k_contract(const float* __restrict__ W) {
    int q = blockIdx.x * 256 + threadIdx.x;
    int d = q % COUT;
    int site = q / COUT;                 // (b*NN+i)*NN+m
    const float* dg = g_diag + (size_t)site * CC;
    const float* rw = g_rows + (size_t)site * CC;
    const float* cl = g_cols + (size_t)site * CC;
    float accD = 0.f, accC = 0.f;
#pragma unroll 8
    for (int c = 0; c < CC; c++) {
        accD += dg[c] * __ldg(W + (2*CC + c)*COUT + d)
              + rw[c] * __ldg(W + (3*CC + c)*COUT + d);
        accC += cl[c] * __ldg(W + (4*CC + c)*COUT + d);
    }
    g_D [(size_t)site*CC + d] = accD;
    g_Cc[(size_t)site*CC + d] = accC;
}

// ---------- fused snconv main (+mask) -> v/w projections or final out ----------
template<int COUT, bool FIN>
__global__ __launch_bounds__(128) void k_conv(float* __restrict__ out_final) {
    int s = blockIdx.x * 128 + threadIdx.x;
    int m = s % NN, j = (s / NN) % NN, i = (s / (NN*NN)) % NN, b = s / (NN*NN*NN);

    const float* tv = g_t + (size_t)s * CC;
    const float* tt = g_t + ((((size_t)b*NN + j)*NN + i)*NN + m) * CC;

    float acc[COUT];
#pragma unroll
    for (int d = 0; d < COUT; d++) acc[d] = 0.f;

#pragma unroll 1
    for (int c0 = 0; c0 < CC; c0 += 8) {
        float ta[8], tb8[8];
        float4 q;
        q = *(const float4*)(tv + c0);     ta[0]=q.x; ta[1]=q.y; ta[2]=q.z; ta[3]=q.w;
        q = *(const float4*)(tv + c0 + 4); ta[4]=q.x; ta[5]=q.y; ta[6]=q.z; ta[7]=q.w;
        q = *(const float4*)(tt + c0);     tb8[0]=q.x; tb8[1]=q.y; tb8[2]=q.z; tb8[3]=q.w;
        q = *(const float4*)(tt + c0 + 4); tb8[4]=q.x; tb8[5]=q.y; tb8[6]=q.z; tb8[7]=q.w;
#pragma unroll
        for (int cc = 0; cc < 8; cc++) {
            const float* w0 = cb + (c0 + cc)*COUT;
            const float* w1 = cb + CC*COUT + (c0 + cc)*COUT;
#pragma unroll
            for (int d = 0; d < COUT; d++)
                acc[d] += ta[cc]*w0[d] + tb8[cc]*w1[d];
        }
    }

    float mv = g_nv[b*NN+i] * g_nv[b*NN+j] * g_nv[b*NN+m];
    const float* Dp = g_D  + ((size_t)(b*NN + i)*NN + m)*CC;
    const float* Cp = g_Cc + ((size_t)(b*NN + j)*NN + m)*CC;
    const float* Gp = g_G  + (b*NN + m)*CC;
#pragma unroll
    for (int d = 0; d < COUT; d++)
        acc[d] = (acc[d] + Dp[d] + Cp[d] + Gp[d]) * mv;

    if (FIN) {
        float4* op = (float4*)(out_final + (size_t)s * COUT);
#pragma unroll
        for (int q4 = 0; q4 < COUT/4; q4++)
            op[q4] = make_float4(acc[q4*4+0], acc[q4*4+1], acc[q4*4+2], acc[q4*4+3]);
    } else {
        float pr[CC];
#pragma unroll
        for (int e = 0; e < CC; e++) pr[e] = cb[OFF_BV + e];
#pragma unroll 1
        for (int d = 0; d < COUT; d++) {
            float sd = acc[d];
            const float* wv = cb + OFF_WV + d*CC;
#pragma unroll
            for (int e = 0; e < CC; e++) pr[e] += sd * wv[e];
        }
        float4* vp = (float4*)(g_v + (size_t)s * CC);
#pragma unroll
        for (int q4 = 0; q4 < CC/4; q4++)
            vp[q4] = make_float4(pr[q4*4+0], pr[q4*4+1], pr[q4*4+2], pr[q4*4+3]);
#pragma unroll
        for (int e = 0; e < CC; e++) pr[e] = cb[OFF_BW + e];
#pragma unroll 1
        for (int d = 0; d < COUT; d++) {
            float sd = acc[d];
            const float* ww = cb + OFF_WW + d*CC;
#pragma unroll
            for (int e = 0; e < CC; e++) pr[e] += sd * ww[e];
        }
        float4* wp = (float4*)(g_w + (size_t)s * CC);
#pragma unroll
        for (int q4 = 0; q4 < CC/4; q4++)
            wp[q4] = make_float4(pr[q4*4+0], pr[q4*4+1], pr[q4*4+2], pr[q4*4+3]);
    }
}

// ---------- localconv: z = sum_k v⊙w / n, project Wo, relu, mask -> t ----------
#define WS_STRIDE 36
#define DSMEM_BYTES ((8*48*32 + 48*8*WS_STRIDE) * 4)

__global__ __launch_bounds__(128) void k_local() {
    extern __shared__ float sm[];
    float* vs = sm;                 // [8][48][32]
    float* ws = sm + 8*48*32;       // [48][8][WS_STRIDE]
    float* zs = sm;                 // alias after compute: [64][33]

    int blk = blockIdx.x;
    int jt6 = blk % 6, it6 = (blk / 6) % 6, m = (blk / 36) % NN, b = blk / (36*NN);
    int i0 = it6 * 8, j0 = jt6 * 8;
    int tid = threadIdx.x;

    for (int idx = tid; idx < 8*48*8; idx += 128) {
        int r = idx >> 3, c4 = idx & 7;
        int ii = r / 48, k = r % 48;
        float4 val = *(const float4*)(g_v + ((((size_t)b*NN + i0+ii)*NN + k)*NN + m)*CC + c4*4);
        *(float4*)(vs + r*32 + c4*4) = val;
    }
    for (int idx = tid; idx < 48*8*8; idx += 128) {
        int r = idx >> 3, c4 = idx & 7;
        int k = r / 8, jj = r % 8;
        float4 val = *(const float4*)(g_w + ((((size_t)b*NN + k)*NN + j0+jj)*NN + m)*CC + c4*4);
        *(float4*)(ws + r*WS_STRIDE + c4*4) = val;
    }
    __syncthreads();

    int ct = tid & 7, jt = (tid >> 3) & 3, it = tid >> 5;
    float a00[4]={0,0,0,0}, a01[4]={0,0,0,0}, a10[4]={0,0,0,0}, a11[4]={0,0,0,0};

#pragma unroll 4
    for (int k = 0; k < 48; k++) {
        float4 v0 = *(const float4*)(vs + ((it*2+0)*48 + k)*32 + ct*4);
        float4 v1 = *(const float4*)(vs + ((it*2+1)*48 + k)*32 + ct*4);
        float4 w0 = *(const float4*)(ws + (k*8 + jt*2+0)*WS_STRIDE + ct*4);
        float4 w1 = *(const float4*)(ws + (k*8 + jt*2+1)*WS_STRIDE + ct*4);
        a00[0]+=v0.x*w0.x; a00[1]+=v0.y*w0.y; a00[2]+=v0.z*w0.z; a00[3]+=v0.w*w0.w;
        a01[0]+=v0.x*w1.x; a01[1]+=v0.y*w1.y; a01[2]+=v0.z*w1.z; a01[3]+=v0.w*w1.w;
        a10[0]+=v1.x*w0.x; a10[1]+=v1.y*w0.y; a10[2]+=v1.z*w0.z; a10[3]+=v1.w*w0.w;
        a11[0]+=v1.x*w1.x; a11[1]+=v1.y*w1.y; a11[2]+=v1.z*w1.z; a11[3]+=v1.w*w1.w;
    }
    __syncthreads();

#pragma unroll
    for (int q = 0; q < 4; q++) {
        zs[((it*2+0)*8 + (jt*2+0))*33 + ct*4 + q] = a00[q];
        zs[((it*2+0)*8 + (jt*2+1))*33 + ct*4 + q] = a01[q];
        zs[((it*2+1)*8 + (jt*2+0))*33 + ct*4 + q] = a10[q];
        zs[((it*2+1)*8 + (jt*2+1))*33 + ct*4 + q] = a11[q];
    }
    __syncthreads();

    int site = tid >> 1, dh = tid & 1;
    float oa[16];
#pragma unroll
    for (int dd = 0; dd < 16; dd++) oa[dd] = 0.f;
#pragma unroll 4
    for (int c = 0; c < 32; c++) {
        float zv = zs[site*33 + c];
        const float* wo = cb + OFF_WO + c*32 + dh*16;
#pragma unroll
        for (int dd = 0; dd < 16; dd++) oa[dd] += zv * wo[dd];
    }
    int ii = site >> 3, jj = site & 7;
    int gi = i0 + ii, gj = j0 + jj;
    float mv = g_nv[b*NN+gi] * g_nv[b*NN+gj] * g_nv[b*NN+m];
    float res[16];
#pragma unroll
    for (int dd = 0; dd < 16; dd++) {
        float v = oa[dd] * (1.0f/NN) + cb[OFF_BO + dh*16 + dd];
        res[dd] = (v > 0.f ? v : 0.f) * mv;
    }
    float4* op = (float4*)(g_t + ((((size_t)b*NN + gi)*NN + gj)*NN + m)*CC + dh*16);
#pragma unroll
    for (int q4 = 0; q4 < 4; q4++)
        op[q4] = make_float4(res[q4*4+0], res[q4*4+1], res[q4*4+2], res[q4*4+3]);
}

// ---------- host ----------
static void stage_layer(void* const* d_in, int base) {
    cudaMemcpyToSymbolAsync(cb, d_in[base+0], 6144*4, 0,      cudaMemcpyDeviceToDevice, 0); // basic_W
    cudaMemcpyToSymbolAsync(cb, d_in[base+1],   32*4, 6144*4, cudaMemcpyDeviceToDevice, 0); // basic_b
    cudaMemcpyToSymbolAsync(cb, d_in[base+2], 1024*4, OFF_WV*4, cudaMemcpyDeviceToDevice, 0); // lv_W
    cudaMemcpyToSymbolAsync(cb, d_in[base+3],   32*4, OFF_BV*4, cudaMemcpyDeviceToDevice, 0); // lv_b
    cudaMemcpyToSymbolAsync(cb, d_in[base+4], 1024*4, OFF_WW*4, cudaMemcpyDeviceToDevice, 0); // lw_W
    cudaMemcpyToSymbolAsync(cb, d_in[base+5],   32*4, OFF_BW*4, cudaMemcpyDeviceToDevice, 0); // lw_b
    cudaMemcpyToSymbolAsync(cb, d_in[base+6], 1024*4, OFF_WO*4, cudaMemcpyDeviceToDevice, 0); // lo_W
    cudaMemcpyToSymbolAsync(cb, d_in[base+7],   32*4, OFF_BO*4, cudaMemcpyDeviceToDevice, 0); // lo_b
}

extern "C" void kernel_launch(void* const* d_in, const int* in_sizes, int n_in,
                              void* d_out, int out_size) {
    (void)in_sizes; (void)n_in; (void)out_size;
    const float* x = (const float*)d_in[0];
    const void*  mask = d_in[1];

    cudaFuncSetAttribute(k_local, cudaFuncAttributeMaxDynamicSharedMemorySize, DSMEM_BYTES);

    k_detect<<<1, 32>>>((const unsigned char*)mask);
    k_nodevalid<<<1, 256>>>(mask);
    k_build_t<<<NSITES/256, 256>>>(x);

    for (int l = 0; l < 2; l++) {
        const float* W = (const float*)d_in[2 + 8*l];
        stage_layer(d_in, 2 + 8*l);
        k_rowcol<<<2*(NIMC/256), 256>>>();
        k_totG<32><<<BATCH*NN, 32>>>(W);
        k_contract<32><<<(BATCH*NN*NN*32)/256, 256>>>(W);
        k_conv<32, false><<<NSITES/128, 128>>>(nullptr);
        k_local<<<BATCH*NN*36, 128, DSMEM_BYTES>>>();
    }

    const float* Wf = (const float*)d_in[18];
    cudaMemcpyToSymbolAsync(cb, d_in[18], 3072*4, 0,      cudaMemcpyDeviceToDevice, 0); // final_W
    cudaMemcpyToSymbolAsync(cb, d_in[19],   16*4, 3072*4, cudaMemcpyDeviceToDevice, 0); // final_b
    k_rowcol<<<2*(NIMC/256), 256>>>();
    k_totG<16><<<BATCH*NN, 32>>>(Wf);
    k_contract<16><<<(BATCH*NN*NN*16)/256, 256>>>(Wf);
    k_conv<16, true><<<NSITES/128, 128>>>((float*)d_out);
}

// round 4
// speedup vs baseline: 1.4975x; 1.0680x over previous
#include <cuda_runtime.h>

#define NN 48
#define BATCH 4
#define CC 32
#define NSITES (BATCH*NN*NN*NN)
#define TSIZE  ((size_t)NSITES*CC)
#define NIMC   (BATCH*NN*NN*CC)      // 294912

__device__ float g_t[TSIZE];
__device__ float g_v[TSIZE];
__device__ float g_w[TSIZE];
__device__ float g_rows[NIMC];
__device__ float g_cols[NIMC];
__device__ float g_diag[NIMC];
__device__ float g_D [NIMC];
__device__ float g_Cc[NIMC];
__device__ float g_G [BATCH*NN*CC];
__device__ int   g_mask_mode;
__device__ float g_nv[BATCH*NN];

// constant weight staging (floats)
#define OFF_WV 6176
#define OFF_WW 7200
#define OFF_WO 8224
#define OFF_BV 9248
#define OFF_BW 9280
#define OFF_BO 9312
__constant__ float cb[9344];

// ---------- mask dtype detection + node_valid extraction ----------
__global__ void k_detect(const unsigned char* __restrict__ mask) {
    if (threadIdx.x == 0) {
        unsigned char b0 = mask[0], b1 = mask[1];
        int mode;
        if (b0 == 1 && b1 != 0) mode = 0;      // 1-byte bool
        else if (b0 == 1)       mode = 1;      // int32
        else                    mode = 2;      // float32
        g_mask_mode = mode;
    }
}
__global__ void k_nodevalid(const void* __restrict__ mask) {
    int p = threadIdx.x;
    if (p < BATCH*NN) {
        int b = p / NN, i = p % NN;
        size_t idx = (((size_t)b*NN + i)*NN + i)*NN + i;
        int mode = g_mask_mode;
        float v;
        if (mode == 0)      v = ((const unsigned char*)mask)[idx] ? 1.f : 0.f;
        else if (mode == 1) v = ((const int*)mask)[idx] ? 1.f : 0.f;
        else                v = (((const float*)mask)[idx] != 0.f) ? 1.f : 0.f;
        g_nv[p] = v;
    }
}

// ---------- t[b,i,j,m,c] = x[b,i,c]*x[b,j,c]*x[b,m,c] * mask ----------
__global__ __launch_bounds__(256) void k_build_t(const float* __restrict__ x) {
    int s = blockIdx.x * 256 + threadIdx.x;
    int m = s % NN, j = (s / NN) % NN, i = (s / (NN*NN)) % NN, b = s / (NN*NN*NN);
    float mv = g_nv[b*NN+i] * g_nv[b*NN+j] * g_nv[b*NN+m];
    const float4* xi = (const float4*)(x + (b*NN + i)*CC);
    const float4* xj = (const float4*)(x + (b*NN + j)*CC);
    const float4* xm = (const float4*)(x + (b*NN + m)*CC);
    float4* out = (float4*)(g_t + (size_t)s * CC);
#pragma unroll
    for (int q = 0; q < 8; q++) {
        float4 a = xi[q], c = xj[q], d = xm[q], r;
        r.x = a.x*c.x*d.x*mv; r.y = a.y*c.y*d.y*mv;
        r.z = a.z*c.z*d.z*mv; r.w = a.w*c.w*d.w*mv;
        out[q] = r;
    }
}

// ---------- stage 1: rows+diag / cols, one thread per output ----------
__global__ __launch_bounds__(256) void k_rowcol() {
    int blk = blockIdx.x;
    bool docols = blk >= (NIMC/256);
    int p = (docols ? blk - NIMC/256 : blk) * 256 + threadIdx.x;
    int c = p & 31;
    int m = (p >> 5) % NN;
    int a = (p / (32*NN)) % NN;
    int b = p / (32*NN*NN);

    if (!docols) {
        const float* pt = g_t + ((((size_t)b*NN + a)*NN + 0)*NN + m)*CC + c;
        float s0=0.f, s1=0.f, s2=0.f, s3=0.f;
#pragma unroll
        for (int j = 0; j < NN; j += 4) {
            s0 += pt[(size_t)(j+0) * (NN*CC)];
            s1 += pt[(size_t)(j+1) * (NN*CC)];
            s2 += pt[(size_t)(j+2) * (NN*CC)];
            s3 += pt[(size_t)(j+3) * (NN*CC)];
        }
        g_rows[p] = (s0+s1+s2+s3) * (1.0f/NN);
        g_diag[p] = pt[(size_t)a * (NN*CC)];
    } else {
        const float* pt = g_t + ((((size_t)b*NN + 0)*NN + a)*NN + m)*CC + c;
        float s0=0.f, s1=0.f, s2=0.f, s3=0.f;
#pragma unroll
        for (int i = 0; i < NN; i += 4) {
            s0 += pt[(size_t)(i+0) * (NN*NN*CC)];
            s1 += pt[(size_t)(i+1) * (NN*NN*CC)];
            s2 += pt[(size_t)(i+2) * (NN*NN*CC)];
            s3 += pt[(size_t)(i+3) * (NN*NN*CC)];
        }
        g_cols[p] = (s0+s1+s2+s3) * (1.0f/NN);
    }
}

// ---------- stage 2: tot per (b,m) + G contraction ----------
template<int COUT>
__global__ __launch_bounds__(32) void k_totG(const float* __restrict__ W) {
    __shared__ float ts[CC];
    int bm = blockIdx.x;
    int m = bm % NN, b = bm / NN;
    int c = threadIdx.x;
    const float* pr = g_rows + (((size_t)b*NN + 0)*NN + m)*CC + c;
    float s = 0.f;
#pragma unroll
    for (int i = 0; i < NN; i++) s += pr[(size_t)i * (NN*CC)];
    ts[c] = s * (1.0f/NN);
    __syncwarp();
    if (c < COUT) {
        float a = cb[6*CC*COUT + c];
#pragma unroll
        for (int c2 = 0; c2 < CC; c2++)
            a += ts[c2] * __ldg(W + (5*CC + c2)*COUT + c);
        g_G[(b*NN + m)*CC + c] = a;
    }
}

// ---------- stage 3: D = diag*W2 + rows*W3 ; Cc = cols*W4 ----------
template<int COUT>
__global__ __launch_bounds__(256) void k_contract(const float* __restrict__ W) {
    int q = blockIdx.x * 256 + threadIdx.x;
    int d = q % COUT;
    int site = q / COUT;
    const float* dg = g_diag + (size_t)site * CC;
    const float* rw = g_rows + (size_t)site * CC;
    const float* cl = g_cols + (size_t)site * CC;
    float accD = 0.f, accC = 0.f;
#pragma unroll 8
    for (int c = 0; c < CC; c++) {
        accD += dg[c] * __ldg(W + (2*CC + c)*COUT + d)
              + rw[c] * __ldg(W + (3*CC + c)*COUT + d);
        accC += cl[c] * __ldg(W + (4*CC + c)*COUT + d);
    }
    g_D [(size_t)site*CC + d] = accD;
    g_Cc[(size_t)site*CC + d] = accC;
}

// ---------- fused snconv main (+mask) -> v/w projections or final out ----------
// Weights staged in shared memory; all weight reads are uniform LDS.128.
template<int COUT, bool FIN>
__global__ __launch_bounds__(256) void k_conv(float* __restrict__ out_final) {
    // smem: [W0|W1] = 2*CC*COUT floats; layers also [Wv|Ww] = 2*CC*CC floats
    __shared__ float s[FIN ? (2*CC*COUT) : (2*CC*COUT + 2*CC*CC)];
    float4* s4 = (float4*)s;
    const float4* cb4 = (const float4*)cb;

    if (FIN) {
        for (int idx = threadIdx.x; idx < (2*CC*COUT)/4; idx += 256)
            s4[idx] = cb4[idx];
    } else {
        // [0,512): W0|W1 from cb[0..2048); [512,1024): Wv|Ww from cb[6176..8224)
        for (int idx = threadIdx.x; idx < 1024; idx += 256)
            s4[idx] = (idx < 512) ? cb4[idx] : cb4[idx + 1032];
    }
    __syncthreads();

    int sidx = blockIdx.x * 256 + threadIdx.x;
    int m = sidx % NN, j = (sidx / NN) % NN, i = (sidx / (NN*NN)) % NN, b = sidx / (NN*NN*NN);

    const float* tv = g_t + (size_t)sidx * CC;
    const float* tt = g_t + ((((size_t)b*NN + j)*NN + i)*NN + m) * CC;

    float acc[COUT];
#pragma unroll
    for (int d = 0; d < COUT; d++) acc[d] = 0.f;

    const int W1O = (CC*COUT)/4;   // float4 offset of W1

#pragma unroll 1
    for (int c0 = 0; c0 < CC; c0 += 8) {
        float ta[8], tb[8];
        float4 q;
        q = *(const float4*)(tv + c0);     ta[0]=q.x; ta[1]=q.y; ta[2]=q.z; ta[3]=q.w;
        q = *(const float4*)(tv + c0 + 4); ta[4]=q.x; ta[5]=q.y; ta[6]=q.z; ta[7]=q.w;
        q = *(const float4*)(tt + c0);     tb[0]=q.x; tb[1]=q.y; tb[2]=q.z; tb[3]=q.w;
        q = *(const float4*)(tt + c0 + 4); tb[4]=q.x; tb[5]=q.y; tb[6]=q.z; tb[7]=q.w;
#pragma unroll
        for (int cc = 0; cc < 8; cc++) {
            int c = c0 + cc;
#pragma unroll
            for (int d4 = 0; d4 < COUT/4; d4++) {
                float4 w0 = s4[c*(COUT/4) + d4];
                float4 w1 = s4[W1O + c*(COUT/4) + d4];
                acc[d4*4+0] += ta[cc]*w0.x + tb[cc]*w1.x;
                acc[d4*4+1] += ta[cc]*w0.y + tb[cc]*w1.y;
                acc[d4*4+2] += ta[cc]*w0.z + tb[cc]*w1.z;
                acc[d4*4+3] += ta[cc]*w0.w + tb[cc]*w1.w;
            }
        }
    }

    float mv = g_nv[b*NN+i] * g_nv[b*NN+j] * g_nv[b*NN+m];
    const float* Dp = g_D  + ((size_t)(b*NN + i)*NN + m)*CC;
    const float* Cp = g_Cc + ((size_t)(b*NN + j)*NN + m)*CC;
    const float* Gp = g_G  + (b*NN + m)*CC;
#pragma unroll
    for (int d = 0; d < COUT; d++)
        acc[d] = (acc[d] + Dp[d] + Cp[d] + Gp[d]) * mv;

    if (FIN) {
        float4* op = (float4*)(out_final + (size_t)sidx * COUT);
#pragma unroll
        for (int q4 = 0; q4 < COUT/4; q4++)
            op[q4] = make_float4(acc[q4*4+0], acc[q4*4+1], acc[q4*4+2], acc[q4*4+3]);
    } else {
        const int WVO = 512;  // float4 offset of Wv
        const int WWO = 768;  // float4 offset of Ww
        float4 pr[8];
        const float4* bv4 = (const float4*)(cb + OFF_BV);
#pragma unroll
        for (int e4 = 0; e4 < 8; e4++) pr[e4] = bv4[e4];
#pragma unroll 1
        for (int d = 0; d < COUT; d++) {
            float sd = acc[d];
#pragma unroll
            for (int e4 = 0; e4 < 8; e4++) {
                float4 wv = s4[WVO + d*8 + e4];
                pr[e4].x += sd*wv.x; pr[e4].y += sd*wv.y;
                pr[e4].z += sd*wv.z; pr[e4].w += sd*wv.w;
            }
        }
        float4* vp = (float4*)(g_v + (size_t)sidx * CC);
#pragma unroll
        for (int e4 = 0; e4 < 8; e4++) vp[e4] = pr[e4];

        const float4* bw4 = (const float4*)(cb + OFF_BW);
#pragma unroll
        for (int e4 = 0; e4 < 8; e4++) pr[e4] = bw4[e4];
#pragma unroll 1
        for (int d = 0; d < COUT; d++) {
            float sd = acc[d];
#pragma unroll
            for (int e4 = 0; e4 < 8; e4++) {
                float4 ww = s4[WWO + d*8 + e4];
                pr[e4].x += sd*ww.x; pr[e4].y += sd*ww.y;
                pr[e4].z += sd*ww.z; pr[e4].w += sd*ww.w;
            }
        }
        float4* wp = (float4*)(g_w + (size_t)sidx * CC);
#pragma unroll
        for (int e4 = 0; e4 < 8; e4++) wp[e4] = pr[e4];
    }
}

// ---------- localconv: z = sum_k v⊙w / n, project Wo, relu, mask -> t ----------
#define WS_STRIDE 36
#define WOFF (8*48*32 + 48*8*WS_STRIDE)          // float offset of Wo stage
#define DSMEM_BYTES ((WOFF + 1024) * 4)          // 108544 B

__global__ __launch_bounds__(128) void k_local() {
    extern __shared__ float sm[];
    float* vs = sm;                 // [8][48][32]
    float* ws = sm + 8*48*32;       // [48][8][WS_STRIDE]
    float* zs = sm;                 // alias after compute: [64][33]
    float4* wo4 = (float4*)(sm + WOFF);

    int blk = blockIdx.x;
    int jt6 = blk % 6, it6 = (blk / 6) % 6, m = (blk / 36) % NN, b = blk / (36*NN);
    int i0 = it6 * 8, j0 = jt6 * 8;
    int tid = threadIdx.x;

    // stage Wo (1024 floats) from constant
    {
        const float4* src = (const float4*)(cb + OFF_WO);
        wo4[tid*2]     = src[tid*2];
        wo4[tid*2 + 1] = src[tid*2 + 1];
    }

    for (int idx = tid; idx < 8*48*8; idx += 128) {
        int r = idx >> 3, c4 = idx & 7;
        int ii = r / 48, k = r % 48;
        float4 val = *(const float4*)(g_v + ((((size_t)b*NN + i0+ii)*NN + k)*NN + m)*CC + c4*4);
        *(float4*)(vs + r*32 + c4*4) = val;
    }
    for (int idx = tid; idx < 48*8*8; idx += 128) {
        int r = idx >> 3, c4 = idx & 7;
        int k = r / 8, jj = r % 8;
        float4 val = *(const float4*)(g_w + ((((size_t)b*NN + k)*NN + j0+jj)*NN + m)*CC + c4*4);
        *(float4*)(ws + r*WS_STRIDE + c4*4) = val;
    }
    __syncthreads();

    int ct = tid & 7, jt = (tid >> 3) & 3, it = tid >> 5;
    float a00[4]={0,0,0,0}, a01[4]={0,0,0,0}, a10[4]={0,0,0,0}, a11[4]={0,0,0,0};

#pragma unroll 4
    for (int k = 0; k < 48; k++) {
        float4 v0 = *(const float4*)(vs + ((it*2+0)*48 + k)*32 + ct*4);
        float4 v1 = *(const float4*)(vs + ((it*2+1)*48 + k)*32 + ct*4);
        float4 w0 = *(const float4*)(ws + (k*8 + jt*2+0)*WS_STRIDE + ct*4);
        float4 w1 = *(const float4*)(ws + (k*8 + jt*2+1)*WS_STRIDE + ct*4);
        a00[0]+=v0.x*w0.x; a00[1]+=v0.y*w0.y; a00[2]+=v0.z*w0.z; a00[3]+=v0.w*w0.w;
        a01[0]+=v0.x*w1.x; a01[1]+=v0.y*w1.y; a01[2]+=v0.z*w1.z; a01[3]+=v0.w*w1.w;
        a10[0]+=v1.x*w0.x; a10[1]+=v1.y*w0.y; a10[2]+=v1.z*w0.z; a10[3]+=v1.w*w0.w;
        a11[0]+=v1.x*w1.x; a11[1]+=v1.y*w1.y; a11[2]+=v1.z*w1.z; a11[3]+=v1.w*w1.w;
    }
    __syncthreads();

#pragma unroll
    for (int q = 0; q < 4; q++) {
        zs[((it*2+0)*8 + (jt*2+0))*33 + ct*4 + q] = a00[q];
        zs[((it*2+0)*8 + (jt*2+1))*33 + ct*4 + q] = a01[q];
        zs[((it*2+1)*8 + (jt*2+0))*33 + ct*4 + q] = a10[q];
        zs[((it*2+1)*8 + (jt*2+1))*33 + ct*4 + q] = a11[q];
    }
    __syncthreads();

    int site = tid >> 1, dh = tid & 1;
    float4 oa[4];
#pragma unroll
    for (int q = 0; q < 4; q++) oa[q] = make_float4(0.f,0.f,0.f,0.f);
#pragma unroll 4
    for (int c = 0; c < 32; c++) {
        float zv = zs[site*33 + c];
#pragma unroll
        for (int q = 0; q < 4; q++) {
            float4 w = wo4[c*8 + dh*4 + q];
            oa[q].x += zv*w.x; oa[q].y += zv*w.y;
            oa[q].z += zv*w.z; oa[q].w += zv*w.w;
        }
    }
    int ii = site >> 3, jj = site & 7;
    int gi = i0 + ii, gj = j0 + jj;
    float mv = g_nv[b*NN+gi] * g_nv[b*NN+gj] * g_nv[b*NN+m];
    float4* op = (float4*)(g_t + ((((size_t)b*NN + gi)*NN + gj)*NN + m)*CC + dh*16);
#pragma unroll
    for (int q = 0; q < 4; q++) {
        float4 r;
        float* pa = (float*)&oa[q];
        float4 rr;
        float* pr_ = (float*)&rr;
#pragma unroll
        for (int e = 0; e < 4; e++) {
            float vv = pa[e] * (1.0f/NN) + cb[OFF_BO + dh*16 + q*4 + e];
            pr_[e] = (vv > 0.f ? vv : 0.f) * mv;
        }
        r = rr;
        op[q] = r;
    }
}

// ---------- host ----------
static void stage_layer(void* const* d_in, int base) {
    cudaMemcpyToSymbolAsync(cb, d_in[base+0], 6144*4, 0,        cudaMemcpyDeviceToDevice, 0);
    cudaMemcpyToSymbolAsync(cb, d_in[base+1],   32*4, 6144*4,   cudaMemcpyDeviceToDevice, 0);
    cudaMemcpyToSymbolAsync(cb, d_in[base+2], 1024*4, OFF_WV*4, cudaMemcpyDeviceToDevice, 0);
    cudaMemcpyToSymbolAsync(cb, d_in[base+3],   32*4, OFF_BV*4, cudaMemcpyDeviceToDevice, 0);
    cudaMemcpyToSymbolAsync(cb, d_in[base+4], 1024*4, OFF_WW*4, cudaMemcpyDeviceToDevice, 0);
    cudaMemcpyToSymbolAsync(cb, d_in[base+5],   32*4, OFF_BW*4, cudaMemcpyDeviceToDevice, 0);
    cudaMemcpyToSymbolAsync(cb, d_in[base+6], 1024*4, OFF_WO*4, cudaMemcpyDeviceToDevice, 0);
    cudaMemcpyToSymbolAsync(cb, d_in[base+7],   32*4, OFF_BO*4, cudaMemcpyDeviceToDevice, 0);
}

extern "C" void kernel_launch(void* const* d_in, const int* in_sizes, int n_in,
                              void* d_out, int out_size) {
    (void)in_sizes; (void)n_in; (void)out_size;
    const float* x = (const float*)d_in[0];
    const void*  mask = d_in[1];

    cudaFuncSetAttribute(k_local, cudaFuncAttributeMaxDynamicSharedMemorySize, DSMEM_BYTES);

    k_detect<<<1, 32>>>((const unsigned char*)mask);
    k_nodevalid<<<1, 256>>>(mask);
    k_build_t<<<NSITES/256, 256>>>(x);

    for (int l = 0; l < 2; l++) {
        const float* W = (const float*)d_in[2 + 8*l];
        stage_layer(d_in, 2 + 8*l);
        k_rowcol<<<2*(NIMC/256), 256>>>();
        k_totG<32><<<BATCH*NN, 32>>>(W);
        k_contract<32><<<(BATCH*NN*NN*32)/256, 256>>>(W);
        k_conv<32, false><<<NSITES/256, 256>>>(nullptr);
        k_local<<<BATCH*NN*36, 128, DSMEM_BYTES>>>();
    }

    const float* Wf = (const float*)d_in[18];
    cudaMemcpyToSymbolAsync(cb, d_in[18], 3072*4, 0,      cudaMemcpyDeviceToDevice, 0);
    cudaMemcpyToSymbolAsync(cb, d_in[19],   16*4, 3072*4, cudaMemcpyDeviceToDevice, 0);
    k_rowcol<<<2*(NIMC/256), 256>>>();
    k_totG<16><<<BATCH*NN, 32>>>(Wf);
    k_contract<16><<<(BATCH*NN*NN*16)/256, 256>>>(Wf);
    k_conv<16, true><<<NSITES/256, 256>>>((float*)d_out);
}

// round 5
// speedup vs baseline: 1.8737x; 1.2511x over previous
#include <cuda_runtime.h>

#define NN 48
#define BATCH 4
#define CC 32
#define NSITES (BATCH*NN*NN*NN)
#define TSIZE  ((size_t)NSITES*CC)
#define NIMC   (BATCH*NN*NN*CC)

__device__ float g_t[TSIZE];
__device__ float g_v[TSIZE];
__device__ float g_w[TSIZE];
__device__ float g_rows[NIMC];
__device__ float g_D [BATCH*NN*NN*CC];
__device__ float g_Cc[BATCH*NN*NN*CC];
__device__ float g_G [BATCH*NN*CC];
__device__ float g_nv[BATCH*NN];

// ---------- mask dtype detection + node_valid, one kernel ----------
__global__ void k_mask(const void* __restrict__ mask) {
    __shared__ int smode;
    if (threadIdx.x == 0) {
        const unsigned char* mb = (const unsigned char*)mask;
        unsigned char b0 = mb[0], b1 = mb[1];
        int mode;
        if (b0 == 1 && b1 != 0) mode = 0;      // 1-byte bool
        else if (b0 == 1)       mode = 1;      // int32
        else                    mode = 2;      // float32
        smode = mode;
    }
    __syncthreads();
    int p = threadIdx.x;
    if (p < BATCH*NN) {
        int b = p / NN, i = p % NN;
        size_t idx = (((size_t)b*NN + i)*NN + i)*NN + i;
        int mode = smode;
        float v;
        if (mode == 0)      v = ((const unsigned char*)mask)[idx] ? 1.f : 0.f;
        else if (mode == 1) v = ((const int*)mask)[idx] ? 1.f : 0.f;
        else                v = (((const float*)mask)[idx] != 0.f) ? 1.f : 0.f;
        g_nv[p] = v;
    }
}

// ---------- t[b,i,j,m,c] = x[b,i,c]*x[b,j,c]*x[b,m,c] * mask ----------
__global__ __launch_bounds__(256) void k_build_t(const float* __restrict__ x) {
    int s = blockIdx.x * 256 + threadIdx.x;
    int m = s % NN, j = (s / NN) % NN, i = (s / (NN*NN)) % NN, b = s / (NN*NN*NN);
    float mv = g_nv[b*NN+i] * g_nv[b*NN+j] * g_nv[b*NN+m];
    const float4* xi = (const float4*)(x + (b*NN + i)*CC);
    const float4* xj = (const float4*)(x + (b*NN + j)*CC);
    const float4* xm = (const float4*)(x + (b*NN + m)*CC);
    float4* out = (float4*)(g_t + (size_t)s * CC);
#pragma unroll
    for (int q = 0; q < 8; q++) {
        float4 a = xi[q], c = xj[q], d = xm[q], r;
        r.x = a.x*c.x*d.x*mv; r.y = a.y*c.y*d.y*mv;
        r.z = a.z*c.z*d.z*mv; r.w = a.w*c.w*d.w*mv;
        out[q] = r;
    }
}

// ---------- fused: rows/diag/cols reduction + D/Cc contraction ----------
// one warp per (b,a,m) site; thread = (site, c)
template<int COUT>
__global__ __launch_bounds__(256) void k_sums(const float* __restrict__ W) {
    __shared__ float sr[8][CC], sd[8][CC], sc[8][CC];
    int p = blockIdx.x * 256 + threadIdx.x;
    int c = p & 31;
    int m = (p >> 5) % NN;
    int a = (p / (32*NN)) % NN;
    int b = p / (32*NN*NN);
    int ls = threadIdx.x >> 5;

    const float* pr = g_t + ((((size_t)b*NN + a)*NN + 0)*NN + m)*CC + c;   // j stride
    float r0=0.f, r1=0.f, r2=0.f, r3=0.f;
#pragma unroll
    for (int j = 0; j < NN; j += 4) {
        r0 += pr[(size_t)(j+0) * (NN*CC)];
        r1 += pr[(size_t)(j+1) * (NN*CC)];
        r2 += pr[(size_t)(j+2) * (NN*CC)];
        r3 += pr[(size_t)(j+3) * (NN*CC)];
    }
    float rowv  = (r0+r1+r2+r3) * (1.0f/NN);
    float diagv = pr[(size_t)a * (NN*CC)];

    const float* pc = g_t + ((((size_t)b*NN + 0)*NN + a)*NN + m)*CC + c;   // i stride
    float s0=0.f, s1=0.f, s2=0.f, s3=0.f;
#pragma unroll
    for (int i = 0; i < NN; i += 4) {
        s0 += pc[(size_t)(i+0) * (NN*NN*CC)];
        s1 += pc[(size_t)(i+1) * (NN*NN*CC)];
        s2 += pc[(size_t)(i+2) * (NN*NN*CC)];
        s3 += pc[(size_t)(i+3) * (NN*NN*CC)];
    }
    float colv = (s0+s1+s2+s3) * (1.0f/NN);

    g_rows[p] = rowv;
    sr[ls][c] = rowv; sd[ls][c] = diagv; sc[ls][c] = colv;
    __syncthreads();

    if (c < COUT) {
        float accD = 0.f, accC = 0.f;
#pragma unroll 8
        for (int c2 = 0; c2 < CC; c2++) {
            accD += sd[ls][c2] * __ldg(W + (2*CC + c2)*COUT + c)
                  + sr[ls][c2] * __ldg(W + (3*CC + c2)*COUT + c);
            accC += sc[ls][c2] * __ldg(W + (4*CC + c2)*COUT + c);
        }
        int site = p >> 5;
        g_D [(size_t)site*COUT + c] = accD;
        g_Cc[(size_t)site*COUT + c] = accC;
    }
}

// ---------- tot per (b,m) + G contraction (+basic bias) ----------
template<int COUT>
__global__ __launch_bounds__(32) void k_totG(const float* __restrict__ W,
                                             const float* __restrict__ bb) {
    __shared__ float ts[CC];
    int bm = blockIdx.x;
    int m = bm % NN, b = bm / NN;
    int c = threadIdx.x;
    const float* pr = g_rows + (((size_t)b*NN + 0)*NN + m)*CC + c;
    float s = 0.f;
#pragma unroll
    for (int i = 0; i < NN; i++) s += pr[(size_t)i * (NN*CC)];
    ts[c] = s * (1.0f/NN);
    __syncwarp();
    if (c < COUT) {
        float a = __ldg(bb + c);
#pragma unroll
        for (int c2 = 0; c2 < CC; c2++)
            a += ts[c2] * __ldg(W + (5*CC + c2)*COUT + c);
        g_G[(b*NN + m)*CC + c] = a;
    }
}

// ---------- fused snconv main (+mask) -> v/w projections or final out ----------
template<int COUT, bool FIN>
__global__ __launch_bounds__(256) void k_conv(const float* __restrict__ W,
                                              const float* __restrict__ Wv,
                                              const float* __restrict__ bv,
                                              const float* __restrict__ Ww,
                                              const float* __restrict__ bw,
                                              float* __restrict__ out_final) {
    __shared__ float s[FIN ? (2*CC*COUT) : (2*CC*COUT + 2*CC*CC)];
    float4* s4 = (float4*)s;
    {
        const float4* W4  = (const float4*)W;
        if (FIN) {
            for (int idx = threadIdx.x; idx < (2*CC*COUT)/4; idx += 256)
                s4[idx] = W4[idx];
        } else {
            const float4* Wv4 = (const float4*)Wv;
            const float4* Ww4 = (const float4*)Ww;
            for (int idx = threadIdx.x; idx < 1024; idx += 256) {
                float4 val;
                if (idx < 512)      val = W4[idx];
                else if (idx < 768) val = Wv4[idx - 512];
                else                val = Ww4[idx - 768];
                s4[idx] = val;
            }
        }
    }
    __syncthreads();

    int sidx = blockIdx.x * 256 + threadIdx.x;
    int m = sidx % NN, j = (sidx / NN) % NN, i = (sidx / (NN*NN)) % NN, b = sidx / (NN*NN*NN);

    const float* tv = g_t + (size_t)sidx * CC;
    const float* tt = g_t + ((((size_t)b*NN + j)*NN + i)*NN + m) * CC;

    float acc[COUT];
#pragma unroll
    for (int d = 0; d < COUT; d++) acc[d] = 0.f;

    const int W1O = (CC*COUT)/4;

#pragma unroll 1
    for (int c0 = 0; c0 < CC; c0 += 8) {
        float ta[8], tb[8];
        float4 q;
        q = *(const float4*)(tv + c0);     ta[0]=q.x; ta[1]=q.y; ta[2]=q.z; ta[3]=q.w;
        q = *(const float4*)(tv + c0 + 4); ta[4]=q.x; ta[5]=q.y; ta[6]=q.z; ta[7]=q.w;
        q = *(const float4*)(tt + c0);     tb[0]=q.x; tb[1]=q.y; tb[2]=q.z; tb[3]=q.w;
        q = *(const float4*)(tt + c0 + 4); tb[4]=q.x; tb[5]=q.y; tb[6]=q.z; tb[7]=q.w;
#pragma unroll
        for (int cc = 0; cc < 8; cc++) {
            int c = c0 + cc;
#pragma unroll
            for (int d4 = 0; d4 < COUT/4; d4++) {
                float4 w0 = s4[c*(COUT/4) + d4];
                float4 w1 = s4[W1O + c*(COUT/4) + d4];
                acc[d4*4+0] += ta[cc]*w0.x + tb[cc]*w1.x;
                acc[d4*4+1] += ta[cc]*w0.y + tb[cc]*w1.y;
                acc[d4*4+2] += ta[cc]*w0.z + tb[cc]*w1.z;
                acc[d4*4+3] += ta[cc]*w0.w + tb[cc]*w1.w;
            }
        }
    }

    float mv = g_nv[b*NN+i] * g_nv[b*NN+j] * g_nv[b*NN+m];
    const float* Dp = g_D  + ((size_t)(b*NN + i)*NN + m)*COUT;
    const float* Cp = g_Cc + ((size_t)(b*NN + j)*NN + m)*COUT;
    const float* Gp = g_G  + (b*NN + m)*CC;
#pragma unroll
    for (int d = 0; d < COUT; d++)
        acc[d] = (acc[d] + Dp[d] + Cp[d] + Gp[d]) * mv;

    if (FIN) {
        float4* op = (float4*)(out_final + (size_t)sidx * COUT);
#pragma unroll
        for (int q4 = 0; q4 < COUT/4; q4++)
            op[q4] = make_float4(acc[q4*4+0], acc[q4*4+1], acc[q4*4+2], acc[q4*4+3]);
    } else {
        const int WVO = 512, WWO = 768;
        float4 pr[8];
        const float4* bv4 = (const float4*)bv;
#pragma unroll
        for (int e4 = 0; e4 < 8; e4++) pr[e4] = __ldg(bv4 + e4);
#pragma unroll 1
        for (int d = 0; d < COUT; d++) {
            float sd = acc[d];
#pragma unroll
            for (int e4 = 0; e4 < 8; e4++) {
                float4 wv = s4[WVO + d*8 + e4];
                pr[e4].x += sd*wv.x; pr[e4].y += sd*wv.y;
                pr[e4].z += sd*wv.z; pr[e4].w += sd*wv.w;
            }
        }
        float4* vp = (float4*)(g_v + (size_t)sidx * CC);
#pragma unroll
        for (int e4 = 0; e4 < 8; e4++) vp[e4] = pr[e4];

        const float4* bw4 = (const float4*)bw;
#pragma unroll
        for (int e4 = 0; e4 < 8; e4++) pr[e4] = __ldg(bw4 + e4);
#pragma unroll 1
        for (int d = 0; d < COUT; d++) {
            float sd = acc[d];
#pragma unroll
            for (int e4 = 0; e4 < 8; e4++) {
                float4 ww = s4[WWO + d*8 + e4];
                pr[e4].x += sd*ww.x; pr[e4].y += sd*ww.y;
                pr[e4].z += sd*ww.z; pr[e4].w += sd*ww.w;
            }
        }
        float4* wp = (float4*)(g_w + (size_t)sidx * CC);
#pragma unroll
        for (int e4 = 0; e4 < 8; e4++) wp[e4] = pr[e4];
    }
}

// ---------- localconv: K-split (2 chunks of 24) for 2x occupancy ----------
#define LK 24
#define WS_STRIDE 36
#define VS_FLOATS (8*LK*32)            // 6144
#define WS_FLOATS (LK*8*WS_STRIDE)     // 6912
#define WO_OFF    (VS_FLOATS + WS_FLOATS)   // 13056
#define DSMEM_BYTES ((WO_OFF + 1024) * 4)   // 56320

__global__ __launch_bounds__(128) void k_local(const float* __restrict__ Wo,
                                               const float* __restrict__ bo) {
    extern __shared__ float sm[];
    float* vs = sm;                  // [8][24][32]
    float* ws = sm + VS_FLOATS;      // [24][8][36]
    float4* wo4 = (float4*)(sm + WO_OFF);
    float* zs = sm;                  // alias after compute: [64][33]

    int blk = blockIdx.x;
    int jt6 = blk % 6, it6 = (blk / 6) % 6, m = (blk / 36) % NN, b = blk / (36*NN);
    int i0 = it6 * 8, j0 = jt6 * 8;
    int tid = threadIdx.x;

    {
        const float4* src = (const float4*)Wo;
        wo4[tid*2]     = __ldg(src + tid*2);
        wo4[tid*2 + 1] = __ldg(src + tid*2 + 1);
    }

    int ct = tid & 7, jt = (tid >> 3) & 3, it = tid >> 5;
    float a00[4]={0,0,0,0}, a01[4]={0,0,0,0}, a10[4]={0,0,0,0}, a11[4]={0,0,0,0};

#pragma unroll 1
    for (int kc = 0; kc < 2; kc++) {
        if (kc) __syncthreads();
        for (int idx = tid; idx < 8*LK*8; idx += 128) {
            int r = idx >> 3, c4 = idx & 7;
            int ii = r / LK, k = r % LK;
            float4 val = *(const float4*)(g_v + ((((size_t)b*NN + i0+ii)*NN + kc*LK + k)*NN + m)*CC + c4*4);
            *(float4*)(vs + r*32 + c4*4) = val;
        }
        for (int idx = tid; idx < LK*8*8; idx += 128) {
            int r = idx >> 3, c4 = idx & 7;
            int k = r / 8, jj = r % 8;
            float4 val = *(const float4*)(g_w + ((((size_t)b*NN + kc*LK + k)*NN + j0+jj)*NN + m)*CC + c4*4);
            *(float4*)(ws + r*WS_STRIDE + c4*4) = val;
        }
        __syncthreads();

#pragma unroll 4
        for (int k = 0; k < LK; k++) {
            float4 v0 = *(const float4*)(vs + ((it*2+0)*LK + k)*32 + ct*4);
            float4 v1 = *(const float4*)(vs + ((it*2+1)*LK + k)*32 + ct*4);
            float4 w0 = *(const float4*)(ws + (k*8 + jt*2+0)*WS_STRIDE + ct*4);
            float4 w1 = *(const float4*)(ws + (k*8 + jt*2+1)*WS_STRIDE + ct*4);
            a00[0]+=v0.x*w0.x; a00[1]+=v0.y*w0.y; a00[2]+=v0.z*w0.z; a00[3]+=v0.w*w0.w;
            a01[0]+=v0.x*w1.x; a01[1]+=v0.y*w1.y; a01[2]+=v0.z*w1.z; a01[3]+=v0.w*w1.w;
            a10[0]+=v1.x*w0.x; a10[1]+=v1.y*w0.y; a10[2]+=v1.z*w0.z; a10[3]+=v1.w*w0.w;
            a11[0]+=v1.x*w1.x; a11[1]+=v1.y*w1.y; a11[2]+=v1.z*w1.z; a11[3]+=v1.w*w1.w;
        }
        __syncthreads();
    }

#pragma unroll
    for (int q = 0; q < 4; q++) {
        zs[((it*2+0)*8 + (jt*2+0))*33 + ct*4 + q] = a00[q];
        zs[((it*2+0)*8 + (jt*2+1))*33 + ct*4 + q] = a01[q];
        zs[((it*2+1)*8 + (jt*2+0))*33 + ct*4 + q] = a10[q];
        zs[((it*2+1)*8 + (jt*2+1))*33 + ct*4 + q] = a11[q];
    }
    __syncthreads();

    int site = tid >> 1, dh = tid & 1;
    float4 oa[4];
#pragma unroll
    for (int q = 0; q < 4; q++) oa[q] = make_float4(0.f,0.f,0.f,0.f);
#pragma unroll 4
    for (int c = 0; c < 32; c++) {
        float zv = zs[site*33 + c];
#pragma unroll
        for (int q = 0; q < 4; q++) {
            float4 w = wo4[c*8 + dh*4 + q];
            oa[q].x += zv*w.x; oa[q].y += zv*w.y;
            oa[q].z += zv*w.z; oa[q].w += zv*w.w;
        }
    }
    int ii = site >> 3, jj = site & 7;
    int gi = i0 + ii, gj = j0 + jj;
    float mv = g_nv[b*NN+gi] * g_nv[b*NN+gj] * g_nv[b*NN+m];
    float4* op = (float4*)(g_t + ((((size_t)b*NN + gi)*NN + gj)*NN + m)*CC + dh*16);
#pragma unroll
    for (int q = 0; q < 4; q++) {
        float* pa = (float*)&oa[q];
        float4 rr;
        float* pr_ = (float*)&rr;
#pragma unroll
        for (int e = 0; e < 4; e++) {
            float vv = pa[e] * (1.0f/NN) + __ldg(bo + dh*16 + q*4 + e);
            pr_[e] = (vv > 0.f ? vv : 0.f) * mv;
        }
        op[q] = rr;
    }
}

// ---------- host ----------
extern "C" void kernel_launch(void* const* d_in, const int* in_sizes, int n_in,
                              void* d_out, int out_size) {
    (void)in_sizes; (void)n_in; (void)out_size;
    const float* x    = (const float*)d_in[0];
    const void*  mask = d_in[1];

    cudaFuncSetAttribute(k_local, cudaFuncAttributeMaxDynamicSharedMemorySize, DSMEM_BYTES);

    k_mask<<<1, 192>>>(mask);
    k_build_t<<<NSITES/256, 256>>>(x);

    for (int l = 0; l < 2; l++) {
        const float* W  = (const float*)d_in[2 + 8*l];
        const float* bb = (const float*)d_in[3 + 8*l];
        const float* Wv = (const float*)d_in[4 + 8*l];
        const float* bv = (const float*)d_in[5 + 8*l];
        const float* Ww = (const float*)d_in[6 + 8*l];
        const float* bw = (const float*)d_in[7 + 8*l];
        const float* Wo = (const float*)d_in[8 + 8*l];
        const float* bo = (const float*)d_in[9 + 8*l];
        k_sums<32><<<NIMC/256, 256>>>(W);
        k_totG<32><<<BATCH*NN, 32>>>(W, bb);
        k_conv<32, false><<<NSITES/256, 256>>>(W, Wv, bv, Ww, bw, nullptr);
        k_local<<<BATCH*NN*36, 128, DSMEM_BYTES>>>(Wo, bo);
    }

    const float* Wf  = (const float*)d_in[18];
    const float* bf  = (const float*)d_in[19];
    k_sums<16><<<NIMC/256, 256>>>(Wf);
    k_totG<16><<<BATCH*NN, 32>>>(Wf, bf);
    k_conv<16, true><<<NSITES/256, 256>>>(Wf, nullptr, nullptr, nullptr, nullptr, (float*)d_out);
}

// round 6
// speedup vs baseline: 2.1955x; 1.1718x over previous
#include <cuda_runtime.h>

#define NN 48
#define BATCH 4
#define CC 32
#define NSITES (BATCH*NN*NN*NN)
#define TSIZE  ((size_t)NSITES*CC)
#define NIMC   (BATCH*NN*NN*CC)

typedef unsigned long long u64t;

__device__ __forceinline__ u64t f2pack(float lo, float hi) {
    u64t r; asm("mov.b64 %0, {%1, %2};" : "=l"(r) : "f"(lo), "f"(hi)); return r;
}
__device__ __forceinline__ float2 f2unpack(u64t v) {
    float2 r; asm("mov.b64 {%0, %1}, %2;" : "=f"(r.x), "=f"(r.y) : "l"(v)); return r;
}
__device__ __forceinline__ void f2fma(u64t& d, u64t a, u64t b) {
    asm("fma.rn.f32x2 %0, %1, %2, %0;" : "+l"(d) : "l"(a), "l"(b));
}
__device__ __forceinline__ u64t f2add(u64t a, u64t b) {
    u64t r; asm("add.rn.f32x2 %0, %1, %2;" : "=l"(r) : "l"(a), "l"(b)); return r;
}
__device__ __forceinline__ u64t f2mul(u64t a, u64t b) {
    u64t r; asm("mul.rn.f32x2 %0, %1, %2;" : "=l"(r) : "l"(a), "l"(b)); return r;
}

__device__ float g_t[TSIZE];
__device__ float g_v[TSIZE];
__device__ float g_w[TSIZE];
__device__ float g_rows[NIMC];
__device__ float g_D [BATCH*NN*NN*CC];
__device__ float g_Cc[BATCH*NN*NN*CC];
__device__ float g_G [BATCH*NN*CC];
__device__ float g_nv[BATCH*NN];

// ---------- mask dtype detection + node_valid ----------
__global__ void k_mask(const void* __restrict__ mask) {
    __shared__ int smode;
    if (threadIdx.x == 0) {
        const unsigned char* mb = (const unsigned char*)mask;
        unsigned char b0 = mb[0], b1 = mb[1];
        int mode;
        if (b0 == 1 && b1 != 0) mode = 0;
        else if (b0 == 1)       mode = 1;
        else                    mode = 2;
        smode = mode;
    }
    __syncthreads();
    int p = threadIdx.x;
    if (p < BATCH*NN) {
        int b = p / NN, i = p % NN;
        size_t idx = (((size_t)b*NN + i)*NN + i)*NN + i;
        int mode = smode;
        float v;
        if (mode == 0)      v = ((const unsigned char*)mask)[idx] ? 1.f : 0.f;
        else if (mode == 1) v = ((const int*)mask)[idx] ? 1.f : 0.f;
        else                v = (((const float*)mask)[idx] != 0.f) ? 1.f : 0.f;
        g_nv[p] = v;
    }
}

// ---------- t build ----------
__global__ __launch_bounds__(256) void k_build_t(const float* __restrict__ x) {
    int s = blockIdx.x * 256 + threadIdx.x;
    int m = s % NN, j = (s / NN) % NN, i = (s / (NN*NN)) % NN, b = s / (NN*NN*NN);
    float mv = g_nv[b*NN+i] * g_nv[b*NN+j] * g_nv[b*NN+m];
    const float4* xi = (const float4*)(x + (b*NN + i)*CC);
    const float4* xj = (const float4*)(x + (b*NN + j)*CC);
    const float4* xm = (const float4*)(x + (b*NN + m)*CC);
    float4* out = (float4*)(g_t + (size_t)s * CC);
#pragma unroll
    for (int q = 0; q < 8; q++) {
        float4 a = xi[q], c = xj[q], d = xm[q], r;
        r.x = a.x*c.x*d.x*mv; r.y = a.y*c.y*d.y*mv;
        r.z = a.z*c.z*d.z*mv; r.w = a.w*c.w*d.w*mv;
        out[q] = r;
    }
}

// ---------- fused rows/diag/cols + D/Cc contraction ----------
template<int COUT>
__global__ __launch_bounds__(256) void k_sums(const float* __restrict__ W) {
    __shared__ float sr[8][CC], sd[8][CC], sc[8][CC];
    int p = blockIdx.x * 256 + threadIdx.x;
    int c = p & 31;
    int m = (p >> 5) % NN;
    int a = (p / (32*NN)) % NN;
    int b = p / (32*NN*NN);
    int ls = threadIdx.x >> 5;

    const float* pr = g_t + ((((size_t)b*NN + a)*NN + 0)*NN + m)*CC + c;
    float r0=0.f, r1=0.f, r2=0.f, r3=0.f;
#pragma unroll
    for (int j = 0; j < NN; j += 4) {
        r0 += pr[(size_t)(j+0) * (NN*CC)];
        r1 += pr[(size_t)(j+1) * (NN*CC)];
        r2 += pr[(size_t)(j+2) * (NN*CC)];
        r3 += pr[(size_t)(j+3) * (NN*CC)];
    }
    float rowv  = (r0+r1+r2+r3) * (1.0f/NN);
    float diagv = pr[(size_t)a * (NN*CC)];

    const float* pc = g_t + ((((size_t)b*NN + 0)*NN + a)*NN + m)*CC + c;
    float s0=0.f, s1=0.f, s2=0.f, s3=0.f;
#pragma unroll
    for (int i = 0; i < NN; i += 4) {
        s0 += pc[(size_t)(i+0) * (NN*NN*CC)];
        s1 += pc[(size_t)(i+1) * (NN*NN*CC)];
        s2 += pc[(size_t)(i+2) * (NN*NN*CC)];
        s3 += pc[(size_t)(i+3) * (NN*NN*CC)];
    }
    float colv = (s0+s1+s2+s3) * (1.0f/NN);

    g_rows[p] = rowv;
    sr[ls][c] = rowv; sd[ls][c] = diagv; sc[ls][c] = colv;
    __syncthreads();

    if (c < COUT) {
        float accD = 0.f, accC = 0.f;
#pragma unroll 8
        for (int c2 = 0; c2 < CC; c2++) {
            accD += sd[ls][c2] * __ldg(W + (2*CC + c2)*COUT + c)
                  + sr[ls][c2] * __ldg(W + (3*CC + c2)*COUT + c);
            accC += sc[ls][c2] * __ldg(W + (4*CC + c2)*COUT + c);
        }
        int site = p >> 5;
        g_D [(size_t)site*COUT + c] = accD;
        g_Cc[(size_t)site*COUT + c] = accC;
    }
}

// ---------- tot per (b,m) + G ----------
template<int COUT>
__global__ __launch_bounds__(32) void k_totG(const float* __restrict__ W,
                                             const float* __restrict__ bb) {
    __shared__ float ts[CC];
    int bm = blockIdx.x;
    int m = bm % NN, b = bm / NN;
    int c = threadIdx.x;
    const float* pr = g_rows + (((size_t)b*NN + 0)*NN + m)*CC + c;
    float s = 0.f;
#pragma unroll
    for (int i = 0; i < NN; i++) s += pr[(size_t)i * (NN*CC)];
    ts[c] = s * (1.0f/NN);
    __syncwarp();
    if (c < COUT) {
        float a = __ldg(bb + c);
#pragma unroll
        for (int c2 = 0; c2 < CC; c2++)
            a += ts[c2] * __ldg(W + (5*CC + c2)*COUT + c);
        g_G[(b*NN + m)*CC + c] = a;
    }
}

// ---------- fused snconv main + projections (f32x2 packed math) ----------
template<int COUT, bool FIN>
__global__ __launch_bounds__(256) void k_conv(const float* __restrict__ W,
                                              const float* __restrict__ Wv,
                                              const float* __restrict__ bv,
                                              const float* __restrict__ Ww,
                                              const float* __restrict__ bw,
                                              float* __restrict__ out_final) {
    __shared__ __align__(16) float s[FIN ? (2*CC*COUT) : (2*CC*COUT + 2*CC*CC)];
    float4* s4 = (float4*)s;
    {
        const float4* W4 = (const float4*)W;
        if (FIN) {
            for (int idx = threadIdx.x; idx < (2*CC*COUT)/4; idx += 256)
                s4[idx] = W4[idx];
        } else {
            const float4* Wv4 = (const float4*)Wv;
            const float4* Ww4 = (const float4*)Ww;
            for (int idx = threadIdx.x; idx < 1024; idx += 256) {
                float4 val;
                if (idx < 512)      val = W4[idx];
                else if (idx < 768) val = Wv4[idx - 512];
                else                val = Ww4[idx - 768];
                s4[idx] = val;
            }
        }
    }
    __syncthreads();

    int sidx = blockIdx.x * 256 + threadIdx.x;
    int m = sidx % NN, j = (sidx / NN) % NN, i = (sidx / (NN*NN)) % NN, b = sidx / (NN*NN*NN);

    const float* tv = g_t + (size_t)sidx * CC;
    const float* tt = g_t + ((((size_t)b*NN + j)*NN + i)*NN + m) * CC;

    u64t acc2[COUT/2];
#pragma unroll
    for (int q = 0; q < COUT/2; q++) acc2[q] = 0ULL;

#pragma unroll 1
    for (int c0 = 0; c0 < CC; c0 += 8) {
        float ta[8], tb[8];
        float4 q4;
        q4 = *(const float4*)(tv + c0);     ta[0]=q4.x; ta[1]=q4.y; ta[2]=q4.z; ta[3]=q4.w;
        q4 = *(const float4*)(tv + c0 + 4); ta[4]=q4.x; ta[5]=q4.y; ta[6]=q4.z; ta[7]=q4.w;
        q4 = *(const float4*)(tt + c0);     tb[0]=q4.x; tb[1]=q4.y; tb[2]=q4.z; tb[3]=q4.w;
        q4 = *(const float4*)(tt + c0 + 4); tb[4]=q4.x; tb[5]=q4.y; tb[6]=q4.z; tb[7]=q4.w;
#pragma unroll
        for (int cc = 0; cc < 8; cc++) {
            int c = c0 + cc;
            u64t ta2 = f2pack(ta[cc], ta[cc]);
            u64t tb2 = f2pack(tb[cc], tb[cc]);
            const ulonglong2* w0p = (const ulonglong2*)(s + c*COUT);
            const ulonglong2* w1p = (const ulonglong2*)(s + CC*COUT + c*COUT);
#pragma unroll
            for (int q = 0; q < COUT/4; q++) {
                ulonglong2 w0 = w0p[q];
                ulonglong2 w1 = w1p[q];
                f2fma(acc2[2*q+0], ta2, w0.x);
                f2fma(acc2[2*q+1], ta2, w0.y);
                f2fma(acc2[2*q+0], tb2, w1.x);
                f2fma(acc2[2*q+1], tb2, w1.y);
            }
        }
    }

    float mv = g_nv[b*NN+i] * g_nv[b*NN+j] * g_nv[b*NN+m];
    u64t mv2 = f2pack(mv, mv);
    const u64t* D2 = (const u64t*)(g_D  + ((size_t)(b*NN + i)*NN + m)*COUT);
    const u64t* C2 = (const u64t*)(g_Cc + ((size_t)(b*NN + j)*NN + m)*COUT);
    const u64t* G2 = (const u64t*)(g_G  + (b*NN + m)*CC);
#pragma unroll
    for (int q = 0; q < COUT/2; q++)
        acc2[q] = f2mul(f2add(acc2[q], f2add(f2add(D2[q], C2[q]), G2[q])), mv2);

    if (FIN) {
        ulonglong2* op = (ulonglong2*)(out_final + (size_t)sidx * COUT);
#pragma unroll
        for (int q = 0; q < COUT/4; q++)
            op[q] = make_ulonglong2(acc2[2*q], acc2[2*q+1]);
    } else {
        const int WVF = 2048, WWF = 3072;   // float offsets in smem
        u64t pr2[CC/2];
        const u64t* bv2 = (const u64t*)bv;
#pragma unroll
        for (int e = 0; e < CC/2; e++) pr2[e] = bv2[e];
#pragma unroll 1
        for (int dq = 0; dq < COUT/2; dq++) {
            float2 ad = f2unpack(acc2[dq]);
            u64t s0 = f2pack(ad.x, ad.x);
            u64t s1 = f2pack(ad.y, ad.y);
            const ulonglong2* wv0 = (const ulonglong2*)(s + WVF + (2*dq+0)*CC);
            const ulonglong2* wv1 = (const ulonglong2*)(s + WVF + (2*dq+1)*CC);
#pragma unroll
            for (int q = 0; q < CC/4; q++) {
                ulonglong2 a = wv0[q];
                ulonglong2 b2 = wv1[q];
                f2fma(pr2[2*q+0], s0, a.x);
                f2fma(pr2[2*q+1], s0, a.y);
                f2fma(pr2[2*q+0], s1, b2.x);
                f2fma(pr2[2*q+1], s1, b2.y);
            }
        }
        ulonglong2* vp = (ulonglong2*)(g_v + (size_t)sidx * CC);
#pragma unroll
        for (int q = 0; q < CC/4; q++)
            vp[q] = make_ulonglong2(pr2[2*q], pr2[2*q+1]);

        const u64t* bw2 = (const u64t*)bw;
#pragma unroll
        for (int e = 0; e < CC/2; e++) pr2[e] = bw2[e];
#pragma unroll 1
        for (int dq = 0; dq < COUT/2; dq++) {
            float2 ad = f2unpack(acc2[dq]);
            u64t s0 = f2pack(ad.x, ad.x);
            u64t s1 = f2pack(ad.y, ad.y);
            const ulonglong2* ww0 = (const ulonglong2*)(s + WWF + (2*dq+0)*CC);
            const ulonglong2* ww1 = (const ulonglong2*)(s + WWF + (2*dq+1)*CC);
#pragma unroll
            for (int q = 0; q < CC/4; q++) {
                ulonglong2 a = ww0[q];
                ulonglong2 b2 = ww1[q];
                f2fma(pr2[2*q+0], s0, a.x);
                f2fma(pr2[2*q+1], s0, a.y);
                f2fma(pr2[2*q+0], s1, b2.x);
                f2fma(pr2[2*q+1], s1, b2.y);
            }
        }
        ulonglong2* wp = (ulonglong2*)(g_w + (size_t)sidx * CC);
#pragma unroll
        for (int q = 0; q < CC/4; q++)
            wp[q] = make_ulonglong2(pr2[2*q], pr2[2*q+1]);
    }
}

// ---------- localconv (f32x2 packed z-loop + epilogue) ----------
#define LK 24
#define WS_STRIDE 36
#define VS_FLOATS (8*LK*32)
#define WS_FLOATS (LK*8*WS_STRIDE)
#define WO_OFF    (VS_FLOATS + WS_FLOATS)
#define DSMEM_BYTES ((WO_OFF + 1024) * 4)
#define ZSTRIDE 34

__global__ __launch_bounds__(128) void k_local(const float* __restrict__ Wo,
                                               const float* __restrict__ bo) {
    extern __shared__ __align__(16) float sm[];
    float* vs = sm;
    float* ws = sm + VS_FLOATS;
    float* wo = sm + WO_OFF;
    float* zs = sm;                  // alias after compute: [64][ZSTRIDE]

    int blk = blockIdx.x;
    int jt6 = blk % 6, it6 = (blk / 6) % 6, m = (blk / 36) % NN, b = blk / (36*NN);
    int i0 = it6 * 8, j0 = jt6 * 8;
    int tid = threadIdx.x;

    {
        float4* wo4 = (float4*)wo;
        const float4* src = (const float4*)Wo;
        wo4[tid*2]     = __ldg(src + tid*2);
        wo4[tid*2 + 1] = __ldg(src + tid*2 + 1);
    }

    int ct = tid & 7, jt = (tid >> 3) & 3, it = tid >> 5;
    u64t a00[2]={0,0}, a01[2]={0,0}, a10[2]={0,0}, a11[2]={0,0};

#pragma unroll 1
    for (int kc = 0; kc < 2; kc++) {
        if (kc) __syncthreads();
        for (int idx = tid; idx < 8*LK*8; idx += 128) {
            int r = idx >> 3, c4 = idx & 7;
            int ii = r / LK, k = r % LK;
            float4 val = *(const float4*)(g_v + ((((size_t)b*NN + i0+ii)*NN + kc*LK + k)*NN + m)*CC + c4*4);
            *(float4*)(vs + r*32 + c4*4) = val;
        }
        for (int idx = tid; idx < LK*8*8; idx += 128) {
            int r = idx >> 3, c4 = idx & 7;
            int k = r / 8, jj = r % 8;
            float4 val = *(const float4*)(g_w + ((((size_t)b*NN + kc*LK + k)*NN + j0+jj)*NN + m)*CC + c4*4);
            *(float4*)(ws + r*WS_STRIDE + c4*4) = val;
        }
        __syncthreads();

#pragma unroll 4
        for (int k = 0; k < LK; k++) {
            ulonglong2 v0 = *(const ulonglong2*)(vs + ((it*2+0)*LK + k)*32 + ct*4);
            ulonglong2 v1 = *(const ulonglong2*)(vs + ((it*2+1)*LK + k)*32 + ct*4);
            ulonglong2 w0 = *(const ulonglong2*)(ws + (k*8 + jt*2+0)*WS_STRIDE + ct*4);
            ulonglong2 w1 = *(const ulonglong2*)(ws + (k*8 + jt*2+1)*WS_STRIDE + ct*4);
            f2fma(a00[0], v0.x, w0.x); f2fma(a00[1], v0.y, w0.y);
            f2fma(a01[0], v0.x, w1.x); f2fma(a01[1], v0.y, w1.y);
            f2fma(a10[0], v1.x, w0.x); f2fma(a10[1], v1.y, w0.y);
            f2fma(a11[0], v1.x, w1.x); f2fma(a11[1], v1.y, w1.y);
        }
        __syncthreads();
    }

    {
        u64t* z0 = (u64t*)(zs + ((it*2+0)*8 + (jt*2+0))*ZSTRIDE + ct*4);
        u64t* z1 = (u64t*)(zs + ((it*2+0)*8 + (jt*2+1))*ZSTRIDE + ct*4);
        u64t* z2 = (u64t*)(zs + ((it*2+1)*8 + (jt*2+0))*ZSTRIDE + ct*4);
        u64t* z3 = (u64t*)(zs + ((it*2+1)*8 + (jt*2+1))*ZSTRIDE + ct*4);
        z0[0] = a00[0]; z0[1] = a00[1];
        z1[0] = a01[0]; z1[1] = a01[1];
        z2[0] = a10[0]; z2[1] = a10[1];
        z3[0] = a11[0]; z3[1] = a11[1];
    }
    __syncthreads();

    int site = tid >> 1, dh = tid & 1;
    u64t oa[8];
#pragma unroll
    for (int q = 0; q < 8; q++) oa[q] = 0ULL;
#pragma unroll 4
    for (int c = 0; c < 32; c++) {
        float zv = zs[site*ZSTRIDE + c];
        u64t zv2 = f2pack(zv, zv);
        const ulonglong2* wrow = (const ulonglong2*)(wo + c*32 + dh*16);
#pragma unroll
        for (int q = 0; q < 4; q++) {
            ulonglong2 w = wrow[q];
            f2fma(oa[2*q+0], zv2, w.x);
            f2fma(oa[2*q+1], zv2, w.y);
        }
    }
    int ii = site >> 3, jj = site & 7;
    int gi = i0 + ii, gj = j0 + jj;
    float mv = g_nv[b*NN+gi] * g_nv[b*NN+gj] * g_nv[b*NN+m];
    float* op = g_t + ((((size_t)b*NN + gi)*NN + gj)*NN + m)*CC + dh*16;
#pragma unroll
    for (int q = 0; q < 8; q++) {
        float2 p = f2unpack(oa[q]);
        float v0 = p.x * (1.0f/NN) + __ldg(bo + dh*16 + 2*q+0);
        float v1 = p.y * (1.0f/NN) + __ldg(bo + dh*16 + 2*q+1);
        v0 = (v0 > 0.f ? v0 : 0.f) * mv;
        v1 = (v1 > 0.f ? v1 : 0.f) * mv;
        *(float2*)(op + 2*q) = make_float2(v0, v1);
    }
}

// ---------- host ----------
extern "C" void kernel_launch(void* const* d_in, const int* in_sizes, int n_in,
                              void* d_out, int out_size) {
    (void)in_sizes; (void)n_in; (void)out_size;
    const float* x    = (const float*)d_in[0];
    const void*  mask = d_in[1];

    cudaFuncSetAttribute(k_local, cudaFuncAttributeMaxDynamicSharedMemorySize, DSMEM_BYTES);

    k_mask<<<1, 192>>>(mask);
    k_build_t<<<NSITES/256, 256>>>(x);

    for (int l = 0; l < 2; l++) {
        const float* W  = (const float*)d_in[2 + 8*l];
        const float* bb = (const float*)d_in[3 + 8*l];
        const float* Wv = (const float*)d_in[4 + 8*l];
        const float* bv = (const float*)d_in[5 + 8*l];
        const float* Ww = (const float*)d_in[6 + 8*l];
        const float* bw = (const float*)d_in[7 + 8*l];
        const float* Wo = (const float*)d_in[8 + 8*l];
        const float* bo = (const float*)d_in[9 + 8*l];
        k_sums<32><<<NIMC/256, 256>>>(W);
        k_totG<32><<<BATCH*NN, 32>>>(W, bb);
        k_conv<32, false><<<NSITES/256, 256>>>(W, Wv, bv, Ww, bw, nullptr);
        k_local<<<BATCH*NN*36, 128, DSMEM_BYTES>>>(Wo, bo);
    }

    const float* Wf  = (const float*)d_in[18];
    const float* bf  = (const float*)d_in[19];
    k_sums<16><<<NIMC/256, 256>>>(Wf);
    k_totG<16><<<BATCH*NN, 32>>>(Wf, bf);
    k_conv<16, true><<<NSITES/256, 256>>>(Wf, nullptr, nullptr, nullptr, nullptr, (float*)d_out);
}

// round 7
// speedup vs baseline: 2.1965x; 1.0004x over previous
#include <cuda_runtime.h>

#define NN 48
#define BATCH 4
#define CC 32
#define NSITES (BATCH*NN*NN*NN)
#define TSIZE  ((size_t)NSITES*CC)
#define NIMC   (BATCH*NN*NN*CC)
#define TOTSZ  (BATCH*NN*CC)

typedef unsigned long long u64t;

__device__ __forceinline__ u64t f2pack(float lo, float hi) {
    u64t r; asm("mov.b64 %0, {%1, %2};" : "=l"(r) : "f"(lo), "f"(hi)); return r;
}
__device__ __forceinline__ float2 f2unpack(u64t v) {
    float2 r; asm("mov.b64 {%0, %1}, %2;" : "=f"(r.x), "=f"(r.y) : "l"(v)); return r;
}
__device__ __forceinline__ void f2fma(u64t& d, u64t a, u64t b) {
    asm("fma.rn.f32x2 %0, %1, %2, %0;" : "+l"(d) : "l"(a), "l"(b));
}
__device__ __forceinline__ u64t f2add(u64t a, u64t b) {
    u64t r; asm("add.rn.f32x2 %0, %1, %2;" : "=l"(r) : "l"(a), "l"(b)); return r;
}
__device__ __forceinline__ u64t f2mul(u64t a, u64t b) {
    u64t r; asm("mul.rn.f32x2 %0, %1, %2;" : "=l"(r) : "l"(a), "l"(b)); return r;
}

__device__ float g_t[TSIZE];
__device__ float g_v[TSIZE];
__device__ float g_w[TSIZE];
__device__ float g_D [NIMC];
__device__ float g_Cc[NIMC];
__device__ float g_tot[3*TOTSZ];
__device__ float g_nv[BATCH*NN];

// ---------- mask detect + node_valid + zero tot accumulators ----------
__global__ void k_mask(const void* __restrict__ mask) {
    __shared__ int smode;
    if (threadIdx.x == 0) {
        const unsigned char* mb = (const unsigned char*)mask;
        unsigned char b0 = mb[0], b1 = mb[1];
        int mode;
        if (b0 == 1 && b1 != 0) mode = 0;
        else if (b0 == 1)       mode = 1;
        else                    mode = 2;
        smode = mode;
    }
    __syncthreads();
    int p = threadIdx.x;
    if (p < BATCH*NN) {
        int b = p / NN, i = p % NN;
        size_t idx = (((size_t)b*NN + i)*NN + i)*NN + i;
        int mode = smode;
        float v;
        if (mode == 0)      v = ((const unsigned char*)mask)[idx] ? 1.f : 0.f;
        else if (mode == 1) v = ((const int*)mask)[idx] ? 1.f : 0.f;
        else                v = (((const float*)mask)[idx] != 0.f) ? 1.f : 0.f;
        g_nv[p] = v;
    }
    for (int q = threadIdx.x; q < 3*TOTSZ; q += 1024) g_tot[q] = 0.f;
}

// ---------- t build ----------
__global__ __launch_bounds__(256) void k_build_t(const float* __restrict__ x) {
    int s = blockIdx.x * 256 + threadIdx.x;
    int m = s % NN, j = (s / NN) % NN, i = (s / (NN*NN)) % NN, b = s / (NN*NN*NN);
    float mv = g_nv[b*NN+i] * g_nv[b*NN+j] * g_nv[b*NN+m];
    const float4* xi = (const float4*)(x + (b*NN + i)*CC);
    const float4* xj = (const float4*)(x + (b*NN + j)*CC);
    const float4* xm = (const float4*)(x + (b*NN + m)*CC);
    float4* out = (float4*)(g_t + (size_t)s * CC);
#pragma unroll
    for (int q = 0; q < 8; q++) {
        float4 a = xi[q], c = xj[q], d = xm[q], r;
        r.x = a.x*c.x*d.x*mv; r.y = a.y*c.y*d.y*mv;
        r.z = a.z*c.z*d.z*mv; r.w = a.w*c.w*d.w*mv;
        out[q] = r;
    }
}

// ---------- rows/diag/cols + D/Cc contraction + atomic tot ----------
template<int COUT>
__global__ __launch_bounds__(256) void k_sums(const float* __restrict__ W, int layer) {
    __shared__ float sr[8][CC], sd[8][CC], sc[8][CC];
    int p = blockIdx.x * 256 + threadIdx.x;
    int c = p & 31;
    int m = (p >> 5) % NN;
    int a = (p / (32*NN)) % NN;
    int b = p / (32*NN*NN);
    int ls = threadIdx.x >> 5;

    const float* pr = g_t + ((((size_t)b*NN + a)*NN + 0)*NN + m)*CC + c;
    float r0=0.f, r1=0.f, r2=0.f, r3=0.f;
#pragma unroll
    for (int j = 0; j < NN; j += 4) {
        r0 += pr[(size_t)(j+0) * (NN*CC)];
        r1 += pr[(size_t)(j+1) * (NN*CC)];
        r2 += pr[(size_t)(j+2) * (NN*CC)];
        r3 += pr[(size_t)(j+3) * (NN*CC)];
    }
    float rowv  = (r0+r1+r2+r3) * (1.0f/NN);
    float diagv = pr[(size_t)a * (NN*CC)];

    const float* pc = g_t + ((((size_t)b*NN + 0)*NN + a)*NN + m)*CC + c;
    float s0=0.f, s1=0.f, s2=0.f, s3=0.f;
#pragma unroll
    for (int i = 0; i < NN; i += 4) {
        s0 += pc[(size_t)(i+0) * (NN*NN*CC)];
        s1 += pc[(size_t)(i+1) * (NN*NN*CC)];
        s2 += pc[(size_t)(i+2) * (NN*NN*CC)];
        s3 += pc[(size_t)(i+3) * (NN*NN*CC)];
    }
    float colv = (s0+s1+s2+s3) * (1.0f/NN);

    atomicAdd(&g_tot[layer*TOTSZ + (b*NN + m)*CC + c], rowv * (1.0f/NN));

    sr[ls][c] = rowv; sd[ls][c] = diagv; sc[ls][c] = colv;
    __syncthreads();

    if (c < COUT) {
        float accD = 0.f, accC = 0.f;
#pragma unroll 8
        for (int c2 = 0; c2 < CC; c2++) {
            accD += sd[ls][c2] * __ldg(W + (2*CC + c2)*COUT + c)
                  + sr[ls][c2] * __ldg(W + (3*CC + c2)*COUT + c);
            accC += sc[ls][c2] * __ldg(W + (4*CC + c2)*COUT + c);
        }
        int site = p >> 5;
        g_D [(size_t)site*COUT + c] = accD;
        g_Cc[(size_t)site*COUT + c] = accC;
    }
}

// ---------- fused snconv main + G prologue + projections, 2 sites/thread ----------
template<int COUT, bool FIN>
__global__ __launch_bounds__(256) void k_conv(const float* __restrict__ W,
                                              const float* __restrict__ bb,
                                              const float* __restrict__ Wv,
                                              const float* __restrict__ bv,
                                              const float* __restrict__ Ww,
                                              const float* __restrict__ bw,
                                              float* __restrict__ out_final,
                                              int layer) {
    constexpr int WFL = FIN ? (2*CC*COUT) : (2*CC*COUT + 2*CC*CC);
    __shared__ __align__(16) float s[WFL + NN*COUT];
    float4* s4 = (float4*)s;
    {
        const float4* W4 = (const float4*)W;
        if (FIN) {
            for (int idx = threadIdx.x; idx < WFL/4; idx += 256)
                s4[idx] = W4[idx];
        } else {
            const float4* Wv4 = (const float4*)Wv;
            const float4* Ww4 = (const float4*)Ww;
            for (int idx = threadIdx.x; idx < 1024; idx += 256) {
                float4 val;
                if (idx < 512)      val = W4[idx];
                else if (idx < 768) val = Wv4[idx - 512];
                else                val = Ww4[idx - 768];
                s4[idx] = val;
            }
        }
    }
    // G prologue: G[m,d] = bb[d] + tot[b,m,:]·W5
    int bblk = blockIdx.x / ((NN*NN*NN)/512);     // same b for whole block
    const float* tot = g_tot + layer*TOTSZ + bblk*(NN*CC);
    for (int idx = threadIdx.x; idx < NN*COUT; idx += 256) {
        int mm = idx / COUT, d = idx % COUT;
        float a = __ldg(bb + d);
        const float* tr = tot + mm*CC;
#pragma unroll 8
        for (int c = 0; c < CC; c++)
            a += tr[c] * __ldg(W + (5*CC + c)*COUT + d);
        s[WFL + idx] = a;
    }
    __syncthreads();

    int s0i = blockIdx.x * 512 + threadIdx.x;      // site 0
    // decode both sites
    int sidx[2] = { s0i, s0i + 256 };
    const float* tv[2]; const float* tt[2];
    int mi[2], ji[2], ii[2];
#pragma unroll
    for (int st = 0; st < 2; st++) {
        int sx = sidx[st];
        int m = sx % NN, j = (sx / NN) % NN, i = (sx / (NN*NN)) % NN;
        mi[st] = m; ji[st] = j; ii[st] = i;
        tv[st] = g_t + (size_t)sx * CC;
        tt[st] = g_t + ((((size_t)bblk*NN + j)*NN + i)*NN + m) * CC;
    }

    u64t acc2[2][COUT/2];
#pragma unroll
    for (int st = 0; st < 2; st++)
#pragma unroll
        for (int q = 0; q < COUT/2; q++) acc2[st][q] = 0ULL;

#pragma unroll 1
    for (int c0 = 0; c0 < CC; c0 += 8) {
        float ta[2][8], tb[2][8];
#pragma unroll
        for (int st = 0; st < 2; st++) {
            float4 q4;
            q4 = *(const float4*)(tv[st] + c0);     ta[st][0]=q4.x; ta[st][1]=q4.y; ta[st][2]=q4.z; ta[st][3]=q4.w;
            q4 = *(const float4*)(tv[st] + c0 + 4); ta[st][4]=q4.x; ta[st][5]=q4.y; ta[st][6]=q4.z; ta[st][7]=q4.w;
            q4 = *(const float4*)(tt[st] + c0);     tb[st][0]=q4.x; tb[st][1]=q4.y; tb[st][2]=q4.z; tb[st][3]=q4.w;
            q4 = *(const float4*)(tt[st] + c0 + 4); tb[st][4]=q4.x; tb[st][5]=q4.y; tb[st][6]=q4.z; tb[st][7]=q4.w;
        }
#pragma unroll
        for (int cc = 0; cc < 8; cc++) {
            int c = c0 + cc;
            u64t a0 = f2pack(ta[0][cc], ta[0][cc]);
            u64t b0 = f2pack(tb[0][cc], tb[0][cc]);
            u64t a1 = f2pack(ta[1][cc], ta[1][cc]);
            u64t b1 = f2pack(tb[1][cc], tb[1][cc]);
            const ulonglong2* w0p = (const ulonglong2*)(s + c*COUT);
            const ulonglong2* w1p = (const ulonglong2*)(s + CC*COUT + c*COUT);
#pragma unroll
            for (int q = 0; q < COUT/4; q++) {
                ulonglong2 w0 = w0p[q];
                ulonglong2 w1 = w1p[q];
                f2fma(acc2[0][2*q+0], a0, w0.x);
                f2fma(acc2[0][2*q+1], a0, w0.y);
                f2fma(acc2[0][2*q+0], b0, w1.x);
                f2fma(acc2[0][2*q+1], b0, w1.y);
                f2fma(acc2[1][2*q+0], a1, w0.x);
                f2fma(acc2[1][2*q+1], a1, w0.y);
                f2fma(acc2[1][2*q+0], b1, w1.x);
                f2fma(acc2[1][2*q+1], b1, w1.y);
            }
        }
    }

#pragma unroll
    for (int st = 0; st < 2; st++) {
        float mv = g_nv[bblk*NN+ii[st]] * g_nv[bblk*NN+ji[st]] * g_nv[bblk*NN+mi[st]];
        u64t mv2 = f2pack(mv, mv);
        const u64t* D2 = (const u64t*)(g_D  + ((size_t)(bblk*NN + ii[st])*NN + mi[st])*COUT);
        const u64t* C2 = (const u64t*)(g_Cc + ((size_t)(bblk*NN + ji[st])*NN + mi[st])*COUT);
        const u64t* G2 = (const u64t*)(s + WFL + mi[st]*COUT);
#pragma unroll
        for (int q = 0; q < COUT/2; q++)
            acc2[st][q] = f2mul(f2add(acc2[st][q], f2add(f2add(D2[q], C2[q]), G2[q])), mv2);
    }

    if (FIN) {
#pragma unroll
        for (int st = 0; st < 2; st++) {
            ulonglong2* op = (ulonglong2*)(out_final + (size_t)sidx[st] * COUT);
#pragma unroll
            for (int q = 0; q < COUT/4; q++)
                op[q] = make_ulonglong2(acc2[st][2*q], acc2[st][2*q+1]);
        }
    } else {
        const int WVF = 2048, WWF = 3072;
#pragma unroll 1
        for (int st = 0; st < 2; st++) {
            u64t pr2[CC/2];
            const u64t* bv2 = (const u64t*)bv;
#pragma unroll
            for (int e = 0; e < CC/2; e++) pr2[e] = bv2[e];
#pragma unroll 1
            for (int dq = 0; dq < COUT/2; dq++) {
                float2 ad = f2unpack(acc2[st][dq]);
                u64t q0 = f2pack(ad.x, ad.x);
                u64t q1 = f2pack(ad.y, ad.y);
                const ulonglong2* wv0 = (const ulonglong2*)(s + WVF + (2*dq+0)*CC);
                const ulonglong2* wv1 = (const ulonglong2*)(s + WVF + (2*dq+1)*CC);
#pragma unroll
                for (int q = 0; q < CC/4; q++) {
                    ulonglong2 a = wv0[q];
                    ulonglong2 b2 = wv1[q];
                    f2fma(pr2[2*q+0], q0, a.x);
                    f2fma(pr2[2*q+1], q0, a.y);
                    f2fma(pr2[2*q+0], q1, b2.x);
                    f2fma(pr2[2*q+1], q1, b2.y);
                }
            }
            ulonglong2* vp = (ulonglong2*)(g_v + (size_t)sidx[st] * CC);
#pragma unroll
            for (int q = 0; q < CC/4; q++)
                vp[q] = make_ulonglong2(pr2[2*q], pr2[2*q+1]);

            const u64t* bw2 = (const u64t*)bw;
#pragma unroll
            for (int e = 0; e < CC/2; e++) pr2[e] = bw2[e];
#pragma unroll 1
            for (int dq = 0; dq < COUT/2; dq++) {
                float2 ad = f2unpack(acc2[st][dq]);
                u64t q0 = f2pack(ad.x, ad.x);
                u64t q1 = f2pack(ad.y, ad.y);
                const ulonglong2* ww0 = (const ulonglong2*)(s + WWF + (2*dq+0)*CC);
                const ulonglong2* ww1 = (const ulonglong2*)(s + WWF + (2*dq+1)*CC);
#pragma unroll
                for (int q = 0; q < CC/4; q++) {
                    ulonglong2 a = ww0[q];
                    ulonglong2 b2 = ww1[q];
                    f2fma(pr2[2*q+0], q0, a.x);
                    f2fma(pr2[2*q+1], q0, a.y);
                    f2fma(pr2[2*q+0], q1, b2.x);
                    f2fma(pr2[2*q+1], q1, b2.y);
                }
            }
            ulonglong2* wp = (ulonglong2*)(g_w + (size_t)sidx[st] * CC);
#pragma unroll
            for (int q = 0; q < CC/4; q++)
                wp[q] = make_ulonglong2(pr2[2*q], pr2[2*q+1]);
        }
    }
}

// ---------- localconv: 16x16 site tiles, K-split x4, 256 threads ----------
#define LK 12
#define VS_FL (16*LK*32)                 // 6144 floats
#define WS_J_STRIDE 109                  // float4 units per jj row (odd -> bank spread)
#define WS_FL (16*WS_J_STRIDE*4)         // 6976 floats
#define WO_OFFL (VS_FL + WS_FL)          // 13120
#define DS_BYTES ((WO_OFFL + 1024)*4)    // 56576 B
#define ZST 34

__global__ __launch_bounds__(256) void k_local(const float* __restrict__ Wo,
                                               const float* __restrict__ bo) {
    extern __shared__ __align__(16) float sm[];
    float* vs = sm;
    float* ws = sm + VS_FL;
    float* wo = sm + WO_OFFL;
    float* zs = sm;                      // alias after compute: [256][ZST]

    int blk = blockIdx.x;
    int q9 = blk % 9;
    int it3 = q9 / 3, jt3 = q9 % 3;
    int m = (blk / 9) % NN, b = blk / (9*NN);
    int i0 = it3 * 16, j0 = jt3 * 16;
    int tid = threadIdx.x;

    ((float4*)wo)[tid] = __ldg(((const float4*)Wo) + tid);

    int ct = tid & 7, jt = (tid >> 3) & 7, it = tid >> 6;
    u64t acc[4][2][2];
#pragma unroll
    for (int r = 0; r < 4; r++)
#pragma unroll
        for (int d = 0; d < 2; d++) { acc[r][d][0] = 0ULL; acc[r][d][1] = 0ULL; }

#pragma unroll 1
    for (int kc = 0; kc < 4; kc++) {
        if (kc) __syncthreads();
        for (int idx = tid; idx < 16*LK*8; idx += 256) {
            int r = idx >> 3, c4 = idx & 7;
            int iiL = r / LK, k = r % LK;
            float4 val = *(const float4*)(g_v + ((((size_t)b*NN + i0+iiL)*NN + kc*LK + k)*NN + m)*CC + c4*4);
            *((float4*)vs + (iiL*LK + k)*8 + c4) = val;
        }
        for (int idx = tid; idx < 16*LK*8; idx += 256) {
            int r = idx >> 3, c4 = idx & 7;
            int jjL = r / LK, k = r % LK;
            float4 val = *(const float4*)(g_w + ((((size_t)b*NN + kc*LK + k)*NN + j0+jjL)*NN + m)*CC + c4*4);
            *((float4*)ws + jjL*WS_J_STRIDE + k*9 + c4) = val;
        }
        __syncthreads();

#pragma unroll 4
        for (int k = 0; k < LK; k++) {
            ulonglong2 v[4];
#pragma unroll
            for (int r = 0; r < 4; r++)
                v[r] = *((const ulonglong2*)vs + ((it*4+r)*LK + k)*8 + ct);
            ulonglong2 w[2];
#pragma unroll
            for (int d = 0; d < 2; d++)
                w[d] = *((const ulonglong2*)ws + (jt*2+d)*WS_J_STRIDE + k*9 + ct);
#pragma unroll
            for (int r = 0; r < 4; r++)
#pragma unroll
                for (int d = 0; d < 2; d++) {
                    f2fma(acc[r][d][0], v[r].x, w[d].x);
                    f2fma(acc[r][d][1], v[r].y, w[d].y);
                }
        }
    }
    __syncthreads();

#pragma unroll
    for (int r = 0; r < 4; r++)
#pragma unroll
        for (int d = 0; d < 2; d++) {
            int il = it*4 + r, jl = jt*2 + d;
            u64t* zp = (u64t*)(zs + (il*16 + jl)*ZST + ct*4);
            zp[0] = acc[r][d][0];
            zp[1] = acc[r][d][1];
        }
    __syncthreads();

    // epilogue: one site per thread, full 32 outputs
    int site = tid;
    int il = site >> 4, jl = site & 15;
    int gi = i0 + il, gj = j0 + jl;
    u64t oa[16];
#pragma unroll
    for (int q = 0; q < 16; q++) oa[q] = 0ULL;
#pragma unroll 4
    for (int c = 0; c < 32; c++) {
        float zv = zs[site*ZST + c];
        u64t zv2 = f2pack(zv, zv);
        const ulonglong2* wrow = (const ulonglong2*)(wo + c*32);
#pragma unroll
        for (int q = 0; q < 8; q++) {
            ulonglong2 w = wrow[q];
            f2fma(oa[2*q+0], zv2, w.x);
            f2fma(oa[2*q+1], zv2, w.y);
        }
    }
    float mv = g_nv[b*NN+gi] * g_nv[b*NN+gj] * g_nv[b*NN+m];
    float* op = g_t + ((((size_t)b*NN + gi)*NN + gj)*NN + m)*CC;
#pragma unroll
    for (int q = 0; q < 8; q++) {
        float2 p0 = f2unpack(oa[2*q+0]);
        float2 p1 = f2unpack(oa[2*q+1]);
        float e0 = p0.x * (1.0f/NN) + __ldg(bo + 4*q+0);
        float e1 = p0.y * (1.0f/NN) + __ldg(bo + 4*q+1);
        float e2 = p1.x * (1.0f/NN) + __ldg(bo + 4*q+2);
        float e3 = p1.y * (1.0f/NN) + __ldg(bo + 4*q+3);
        e0 = (e0 > 0.f ? e0 : 0.f) * mv;
        e1 = (e1 > 0.f ? e1 : 0.f) * mv;
        e2 = (e2 > 0.f ? e2 : 0.f) * mv;
        e3 = (e3 > 0.f ? e3 : 0.f) * mv;
        *(float4*)(op + 4*q) = make_float4(e0, e1, e2, e3);
    }
}

// ---------- host ----------
extern "C" void kernel_launch(void* const* d_in, const int* in_sizes, int n_in,
                              void* d_out, int out_size) {
    (void)in_sizes; (void)n_in; (void)out_size;
    const float* x    = (const float*)d_in[0];
    const void*  mask = d_in[1];

    cudaFuncSetAttribute(k_local, cudaFuncAttributeMaxDynamicSharedMemorySize, DS_BYTES);

    k_mask<<<1, 1024>>>(mask);
    k_build_t<<<NSITES/256, 256>>>(x);

    for (int l = 0; l < 2; l++) {
        const float* W  = (const float*)d_in[2 + 8*l];
        const float* bb = (const float*)d_in[3 + 8*l];
        const float* Wv = (const float*)d_in[4 + 8*l];
        const float* bv = (const float*)d_in[5 + 8*l];
        const float* Ww = (const float*)d_in[6 + 8*l];
        const float* bw = (const float*)d_in[7 + 8*l];
        const float* Wo = (const float*)d_in[8 + 8*l];
        const float* bo = (const float*)d_in[9 + 8*l];
        k_sums<32><<<NIMC/256, 256>>>(W, l);
        k_conv<32, false><<<NSITES/512, 256>>>(W, bb, Wv, bv, Ww, bw, nullptr, l);
        k_local<<<BATCH*NN*9, 256, DS_BYTES>>>(Wo, bo);
    }

    const float* Wf  = (const float*)d_in[18];
    const float* bf  = (const float*)d_in[19];
    k_sums<16><<<NIMC/256, 256>>>(Wf, 2);
    k_conv<16, true><<<NSITES/512, 256>>>(Wf, bf, nullptr, nullptr, nullptr, nullptr, (float*)d_out, 2);
}